// round 10
// baseline (speedup 1.0000x reference)
#include <cuda_runtime.h>
#include <cuda_bf16.h>
#include <cstdint>

#define NL 2
#define NH 8
#define SEQ 1024
#define HIDX 512
#define HH 4096
#define NE 8
#define FFN 1024
#define NB 4
#define TOK 4096
#define EPSV 1e-5f
#define MAXROWS 4608
#define MAXT 72
#define SMEMSZ 55296

// fp32 buffers
static __device__ float g_v[(size_t)TOK * HH];
static __device__ float g_sc[(size_t)NB * NH * SEQ * SEQ];
static __device__ float g_t1[(size_t)TOK * HIDX];
static __device__ float g_x[(size_t)TOK * HIDX];
static __device__ float g_y[(size_t)TOK * HIDX];
static __device__ float g_h[(size_t)MAXROWS * FFN];
static __device__ int   g_sel[TOK];
static __device__ float g_wsel[TOK];
static __device__ int   g_perm[MAXROWS];
static __device__ int   g_texp[MAXT];

// packed bf16-pair buffers (hi/lo), 16B aligned for cp.async
#define PKA __device__ __align__(16)
static PKA uint32_t g_qh[(size_t)TOK * HH / 2], g_ql[(size_t)TOK * HH / 2];
static PKA uint32_t g_kh[(size_t)TOK * HH / 2], g_kl[(size_t)TOK * HH / 2];
static PKA uint32_t g_vph[(size_t)NB * NH * (SEQ / 2) * HIDX], g_vpl[(size_t)NB * NH * (SEQ / 2) * HIDX];
static PKA uint32_t g_o2h[(size_t)TOK * HH / 2], g_o2l[(size_t)TOK * HH / 2];
static PKA uint32_t g_ath[(size_t)NB * NH * SEQ * SEQ / 2], g_atl[(size_t)NB * NH * SEQ * SEQ / 2];
static PKA uint32_t g_xph[TOK * HIDX / 2], g_xpl[TOK * HIDX / 2];
static PKA uint32_t g_eph[TOK * HIDX / 2], g_epl[TOK * HIDX / 2];
static PKA uint32_t g_wqh[(size_t)NL * 2 * HIDX / 2 * HH], g_wql[(size_t)NL * 2 * HIDX / 2 * HH];
static PKA uint32_t g_wkh[(size_t)NL * 2 * HIDX / 2 * HH], g_wkl[(size_t)NL * 2 * HIDX / 2 * HH];
static PKA uint32_t g_wvh[(size_t)NL * 2 * HIDX / 2 * HH], g_wvl[(size_t)NL * 2 * HIDX / 2 * HH];
static PKA uint32_t g_woh[(size_t)NL * 2 * HH / 2 * HIDX], g_wol[(size_t)NL * 2 * HH / 2 * HIDX];

__device__ __forceinline__ void split2(float x, float y, uint32_t& hi, uint32_t& lo)
{
    __nv_bfloat162 h = __floats2bfloat162_rn(x, y);
    float2 hf = __bfloat1622float2(h);
    __nv_bfloat162 l = __floats2bfloat162_rn(x - hf.x, y - hf.y);
    hi = *(uint32_t*)&h;
    lo = *(uint32_t*)&l;
}

#define MMA_BF16(d, a, b)                                                     \
    asm volatile(                                                             \
        "mma.sync.aligned.m16n8k16.row.col.f32.bf16.bf16.f32 "                \
        "{%0,%1,%2,%3},{%4,%5,%6,%7},{%8,%9},{%0,%1,%2,%3};"                  \
        : "+f"(d[0]), "+f"(d[1]), "+f"(d[2]), "+f"(d[3])                      \
        : "r"(a[0]), "r"(a[1]), "r"(a[2]), "r"(a[3]), "r"(b[0]), "r"(b[1]))

// ---------------------------------------------------------------------------
// Packed split-bf16 tensor-core GEMM with cp.async 3-stage pipeline.
// Exact round-6 inner loop (6218us proven); ONLY change: launch_bounds
// minBlocks=3 to force >=3 blocks/SM (caps regs at 84) for barrier-wait
// latency hiding.
// ---------------------------------------------------------------------------
__global__ void __launch_bounds__(256, 3) bgemm(
    const uint32_t* __restrict__ Ah, const uint32_t* __restrict__ Al,
    int ldaP, long long aSb, long long aSh,
    const uint32_t* __restrict__ Bh, const uint32_t* __restrict__ Bl,
    int ldbB, long long bSb, long long bSh,
    float* __restrict__ C, int ldc, long long cSb, long long cSh,
    uint32_t* __restrict__ Cph, uint32_t* __restrict__ Cpl,
    int ldcP, long long cpSb, long long cpSh,
    const float* __restrict__ bias,
    int K, int transB, int causalSkip, int causalK)
{
    int row0 = blockIdx.y * 128;
    int col0 = blockIdx.x * 64;
    if (causalSkip && col0 >= row0 + 128) return;
    long long zb = blockIdx.z >> 3, zh = blockIdx.z & 7;
    Ah += zb * aSb + zh * aSh;
    Al += zb * aSb + zh * aSh;
    Bh += zb * bSb + zh * bSh;
    Bl += zb * bSb + zh * bSh;

    extern __shared__ uint32_t sm[];
    uint32_t smBase = (uint32_t)__cvta_generic_to_shared(sm);

    int tid = threadIdx.x;
    int warp = tid >> 5, lane = tid & 31;
    int wm0 = (warp >> 1) << 5;
    int wn0 = (warp & 1) << 5;
    int tg = lane & 3, gp = lane >> 2;

    const uint32_t* pAh = Ah + (long long)(row0 + (tid >> 1)) * ldaP + ((tid & 1) << 2);
    const uint32_t* pAl = Al + (long long)(row0 + (tid >> 1)) * ldaP + ((tid & 1) << 2);
    int aOff = (tid >> 1) * 12 + ((tid & 1) << 2);

    const uint32_t* pB;
    int bOff;
    int bBase = (tid < 128) ? 9216 : 11520;
    int tt = tid & 127;
    long long bStep;
    if (!transB) {
        int kp = tt >> 4, cc = (tt & 15) << 2;
        pB = (tid < 128 ? Bh : Bl) + (long long)kp * ldbB + col0 + cc;
        bOff = kp * 72 + cc;
        bStep = ldbB;
    } else {
        int nn = tt >> 1, cc = (tt & 1) << 2;
        pB = (tid < 128 ? Bh : Bl) + (long long)(col0 + nn) * ldbB + cc;
        bOff = nn * 12 + cc;
        bStep = 1;
    }

#define CPA(doff, src)                                                        \
    asm volatile("cp.async.cg.shared.global [%0], [%1], 16;"                  \
                 :: "r"(smBase + ((doff) << 2)), "l"(src))
#define ISSUE(st, kp0)                                                        \
    do {                                                                      \
        CPA((st) * 1536 + aOff, pAh + (kp0));                                 \
        CPA(4608 + (st) * 1536 + aOff, pAl + (kp0));                          \
        CPA(bBase + (st) * 768 + bOff, pB + (long long)(kp0) * bStep);        \
    } while (0)
#define COMMIT asm volatile("cp.async.commit_group;" ::)

    int kend = causalK ? (row0 + 128) : K;
    int niter = kend >> 4;

    ISSUE(0, 0);
    COMMIT;
    if (niter > 1) ISSUE(1, 8);
    COMMIT;

    float acc[2][4][4];
#pragma unroll
    for (int i = 0; i < 2; i++)
#pragma unroll
        for (int j = 0; j < 4; j++)
#pragma unroll
            for (int t = 0; t < 4; t++) acc[i][j][t] = 0.f;

    for (int i = 0; i < niter; i++) {
        if (i + 1 < niter) asm volatile("cp.async.wait_group 1;" ::);
        else               asm volatile("cp.async.wait_group 0;" ::);
        __syncthreads();
        if (i + 2 < niter) {
            int s2 = (i + 2) % 3;
            ISSUE(s2, (i + 2) * 8);
        }
        COMMIT;

        int s = i % 3;
        const uint32_t* aHs = sm + s * 1536;
        const uint32_t* aLs = sm + 4608 + s * 1536;
        const uint32_t* bHs = sm + 9216 + s * 768;
        const uint32_t* bLs = sm + 11520 + s * 768;

        uint32_t aF[2][4], aG[2][4], bF[4][2], bG[4][2];
#pragma unroll
        for (int mt = 0; mt < 2; mt++) {
            int m = wm0 + mt * 16 + gp;
            aF[mt][0] = aHs[m * 12 + tg];
            aF[mt][1] = aHs[(m + 8) * 12 + tg];
            aF[mt][2] = aHs[m * 12 + tg + 4];
            aF[mt][3] = aHs[(m + 8) * 12 + tg + 4];
            aG[mt][0] = aLs[m * 12 + tg];
            aG[mt][1] = aLs[(m + 8) * 12 + tg];
            aG[mt][2] = aLs[m * 12 + tg + 4];
            aG[mt][3] = aLs[(m + 8) * 12 + tg + 4];
        }
        if (!transB) {
#pragma unroll
            for (int nt = 0; nt < 4; nt++) {
                int n = wn0 + nt * 8 + gp;
                bF[nt][0] = bHs[tg * 72 + n];
                bF[nt][1] = bHs[(tg + 4) * 72 + n];
                bG[nt][0] = bLs[tg * 72 + n];
                bG[nt][1] = bLs[(tg + 4) * 72 + n];
            }
        } else {
#pragma unroll
            for (int nt = 0; nt < 4; nt++) {
                int n = wn0 + nt * 8 + gp;
                bF[nt][0] = bHs[n * 12 + tg];
                bF[nt][1] = bHs[n * 12 + tg + 4];
                bG[nt][0] = bLs[n * 12 + tg];
                bG[nt][1] = bLs[n * 12 + tg + 4];
            }
        }
#pragma unroll
        for (int mt = 0; mt < 2; mt++)
#pragma unroll
            for (int nt = 0; nt < 4; nt++) {
                MMA_BF16(acc[mt][nt], aF[mt], bF[nt]);
                MMA_BF16(acc[mt][nt], aF[mt], bG[nt]);
                MMA_BF16(acc[mt][nt], aG[mt], bF[nt]);
            }
    }

    if (Cph) {
        Cph += zb * cpSb + zh * cpSh;
        Cpl += zb * cpSb + zh * cpSh;
#pragma unroll
        for (int mt = 0; mt < 2; mt++) {
            long long r = row0 + wm0 + mt * 16 + gp;
#pragma unroll
            for (int nt = 0; nt < 4; nt++) {
                int c = col0 + wn0 + nt * 8 + tg * 2;
                float b0 = bias ? bias[c] : 0.f;
                float b1 = bias ? bias[c + 1] : 0.f;
                uint32_t h, l;
                split2(acc[mt][nt][0] + b0, acc[mt][nt][1] + b1, h, l);
                Cph[r * ldcP + (c >> 1)] = h;
                Cpl[r * ldcP + (c >> 1)] = l;
                split2(acc[mt][nt][2] + b0, acc[mt][nt][3] + b1, h, l);
                Cph[(r + 8) * ldcP + (c >> 1)] = h;
                Cpl[(r + 8) * ldcP + (c >> 1)] = l;
            }
        }
    } else {
        C += zb * cSb + zh * cSh;
#pragma unroll
        for (int mt = 0; mt < 2; mt++) {
            long long r = row0 + wm0 + mt * 16 + gp;
#pragma unroll
            for (int nt = 0; nt < 4; nt++) {
                int c = col0 + wn0 + nt * 8 + tg * 2;
                float b0 = bias ? bias[c] : 0.f;
                float b1 = bias ? bias[c + 1] : 0.f;
                float2 lo = make_float2(acc[mt][nt][0] + b0, acc[mt][nt][1] + b1);
                float2 hi = make_float2(acc[mt][nt][2] + b0, acc[mt][nt][3] + b1);
                *(float2*)(C + r * ldc + c) = lo;
                *(float2*)(C + (r + 8) * ldc + c) = hi;
            }
        }
    }
#undef CPA
#undef ISSUE
#undef COMMIT
}

// ---------------------------------------------------------------------------
// Pre-split kernels
// ---------------------------------------------------------------------------
__global__ void __launch_bounds__(256) packrows(const float* __restrict__ src,
                                                uint32_t* __restrict__ h, uint32_t* __restrict__ l)
{
    int idx = blockIdx.x * 256 + threadIdx.x;
    float2 v = ((const float2*)src)[idx];
    split2(v.x, v.y, h[idx], l[idx]);
}

__global__ void __launch_bounds__(256) packcols(const float* __restrict__ src,
                                                uint32_t* __restrict__ h, uint32_t* __restrict__ l,
                                                int logN)
{
    int idx = blockIdx.x * 256 + threadIdx.x;
    int kp = idx >> logN;
    int c = idx & ((1 << logN) - 1);
    const float* p = src + (((size_t)kp * 2) << logN) + c;
    split2(p[0], p[1 << logN], h[idx], l[idx]);
}

__global__ void __launch_bounds__(256) packv(const float* __restrict__ v,
                                             uint32_t* __restrict__ h, uint32_t* __restrict__ l)
{
    int idx = blockIdx.x * 256 + threadIdx.x;
    int b  = idx >> 21;
    int hh = (idx >> 18) & 7;
    int jp = (idx >> 9) & 511;
    int d  = idx & 511;
    const float* p = v + (size_t)b * 4194304 + (size_t)hh * 524288 + jp * 1024 + d;
    split2(p[0], p[512], h[idx], l[idx]);
}

// ---------------------------------------------------------------------------
// Softmax over rows of SEQ; writes packed bf16 hi/lo probabilities.
// ---------------------------------------------------------------------------
__global__ void __launch_bounds__(256) softmax_kernel(const float* __restrict__ sc,
                                                      uint32_t* __restrict__ ath,
                                                      uint32_t* __restrict__ atl, int masked)
{
    long long base = (long long)blockIdx.x * SEQ;
    long long pbase = (long long)blockIdx.x * (SEQ / 2);
    int i = blockIdx.x & (SEQ - 1);
    int n = masked ? (i + 1) : SEQ;
    int tid = threadIdx.x;
    __shared__ float red[8];

    float v[2][2];
    float mx = -1e30f;
#pragma unroll
    for (int j = 0; j < 2; j++) {
        int c = (tid + (j << 8)) << 1;
        float2 t = *(const float2*)(sc + base + c);
        v[j][0] = (c < n) ? t.x : -1e30f;
        v[j][1] = (c + 1 < n) ? t.y : -1e30f;
        mx = fmaxf(mx, fmaxf(v[j][0], v[j][1]));
    }
#pragma unroll
    for (int o = 16; o; o >>= 1) mx = fmaxf(mx, __shfl_xor_sync(0xffffffffu, mx, o));
    if ((tid & 31) == 0) red[tid >> 5] = mx;
    __syncthreads();
    mx = red[0];
#pragma unroll
    for (int w = 1; w < 8; w++) mx = fmaxf(mx, red[w]);
    __syncthreads();

    float s = 0.f;
#pragma unroll
    for (int j = 0; j < 2; j++) {
        int c = (tid + (j << 8)) << 1;
        v[j][0] = (c < n) ? __expf(v[j][0] - mx) : 0.f;
        v[j][1] = (c + 1 < n) ? __expf(v[j][1] - mx) : 0.f;
        s += v[j][0] + v[j][1];
    }
#pragma unroll
    for (int o = 16; o; o >>= 1) s += __shfl_xor_sync(0xffffffffu, s, o);
    if ((tid & 31) == 0) red[tid >> 5] = s;
    __syncthreads();
    s = 0.f;
#pragma unroll
    for (int w = 0; w < 8; w++) s += red[w];
    float inv = 1.f / s;
#pragma unroll
    for (int j = 0; j < 2; j++) {
        uint32_t h, l;
        split2(v[j][0] * inv, v[j][1] * inv, h, l);
        ath[pbase + tid + (j << 8)] = h;
        atl[pbase + tid + (j << 8)] = l;
    }
}

// ---------------------------------------------------------------------------
// y = LayerNorm(a + r); also writes packed bf16 hi/lo of y.
// ---------------------------------------------------------------------------
__global__ void __launch_bounds__(256) ln_kernel(
    const float* __restrict__ a, const float* __restrict__ r,
    const float* __restrict__ g, const float* __restrict__ b,
    float* __restrict__ y, uint32_t* __restrict__ yph, uint32_t* __restrict__ ypl)
{
    long long base = (long long)blockIdx.x * HIDX;
    int tid = threadIdx.x;
    int c = tid << 1;
    __shared__ float red[8];

    float2 av = *(const float2*)(a + base + c);
    float2 rv = *(const float2*)(r + base + c);
    float z0 = av.x + rv.x, z1 = av.y + rv.y;
    float s = z0 + z1;
#pragma unroll
    for (int o = 16; o; o >>= 1) s += __shfl_xor_sync(0xffffffffu, s, o);
    if ((tid & 31) == 0) red[tid >> 5] = s;
    __syncthreads();
    s = 0.f;
#pragma unroll
    for (int w = 0; w < 8; w++) s += red[w];
    float m = s * (1.f / HIDX);
    float d0 = z0 - m, d1 = z1 - m;
    float qs = d0 * d0 + d1 * d1;
    __syncthreads();
#pragma unroll
    for (int o = 16; o; o >>= 1) qs += __shfl_xor_sync(0xffffffffu, qs, o);
    if ((tid & 31) == 0) red[tid >> 5] = qs;
    __syncthreads();
    qs = 0.f;
#pragma unroll
    for (int w = 0; w < 8; w++) qs += red[w];
    float inv = rsqrtf(qs * (1.f / HIDX) + EPSV);
    float2 gg = *(const float2*)(g + c);
    float2 bb = *(const float2*)(b + c);
    float o0 = gg.x * d0 * inv + bb.x;
    float o1 = gg.y * d1 * inv + bb.y;
    *(float2*)(y + base + c) = make_float2(o0, o1);
    uint32_t h, l;
    split2(o0, o1, h, l);
    yph[(long long)blockIdx.x * 256 + tid] = h;
    ypl[(long long)blockIdx.x * 256 + tid] = l;
}

// ---------------------------------------------------------------------------
// Gate: softmax over E=8, pick 2nd-largest (faithful TOPK-1 bug).
// ---------------------------------------------------------------------------
__global__ void __launch_bounds__(256) gate_kernel(
    const float* __restrict__ x, const float* __restrict__ gw, const float* __restrict__ gb)
{
    int tok = (blockIdx.x << 3) + (threadIdx.x >> 5);
    int lane = threadIdx.x & 31;
    const float* xr = x + (size_t)tok * HIDX;
    float acc[8] = {0, 0, 0, 0, 0, 0, 0, 0};
    for (int j = lane; j < HIDX; j += 32) {
        float xv = xr[j];
        float4 a0 = *(const float4*)(gw + j * 8);
        float4 a1 = *(const float4*)(gw + j * 8 + 4);
        acc[0] += xv * a0.x; acc[1] += xv * a0.y; acc[2] += xv * a0.z; acc[3] += xv * a0.w;
        acc[4] += xv * a1.x; acc[5] += xv * a1.y; acc[6] += xv * a1.z; acc[7] += xv * a1.w;
    }
#pragma unroll
    for (int e = 0; e < 8; e++)
#pragma unroll
        for (int o = 16; o; o >>= 1) acc[e] += __shfl_xor_sync(0xffffffffu, acc[e], o);
    if (lane == 0) {
        float mx = -1e30f;
#pragma unroll
        for (int e = 0; e < 8; e++) { acc[e] += gb[e]; mx = fmaxf(mx, acc[e]); }
        float p[8];
#pragma unroll
        for (int e = 0; e < 8; e++) p[e] = __expf(acc[e] - mx);
        float v1 = -1.f, v2 = -1.f; int i1 = 0, i2 = 0;
#pragma unroll
        for (int e = 0; e < 8; e++) {
            if (p[e] > v1)      { v2 = v1; i2 = i1; v1 = p[e]; i1 = e; }
            else if (p[e] > v2) { v2 = p[e]; i2 = e; }
        }
        g_sel[tok] = i2;
        g_wsel[tok] = v2 / (v1 + v2);
    }
}

__global__ void __launch_bounds__(256) moe_setup()
{
    __shared__ int cnt[8], cursor[8];
    int tid = threadIdx.x;
    if (tid < 8) cnt[tid] = 0;
    for (int i = tid; i < MAXROWS; i += 256) g_perm[i] = -1;
    __syncthreads();
    for (int i = tid; i < TOK; i += 256) atomicAdd(&cnt[g_sel[i]], 1);
    __syncthreads();
    if (tid == 0) {
        int base = 0, t = 0;
        for (int e = 0; e < 8; e++) {
            cursor[e] = base;
            int tiles = (cnt[e] + 63) >> 6;
            for (int j = 0; j < tiles; j++) g_texp[t++] = e;
            base += tiles << 6;
        }
        for (; t < MAXT; t++) g_texp[t] = -1;
    }
    __syncthreads();
    for (int i = tid; i < TOK; i += 256) {
        int e = g_sel[i];
        int p = atomicAdd(&cursor[e], 1);
        g_perm[p] = i;
    }
}

__global__ void __launch_bounds__(256) moe_gemm1(
    const float* __restrict__ x, const float* __restrict__ w1, const float* __restrict__ b1)
{
    int t = blockIdx.y;
    int e = g_texp[t];
    if (e < 0) return;
    const float* B = w1 + (size_t)e * HIDX * FFN;
    const float* bias = b1 + (size_t)e * FFN;
    int col0 = blockIdx.x << 6;
    __shared__ float As[16][68];
    __shared__ float Bs[16][68];
    __shared__ int rows[64];
    int tid = threadIdx.x;
    if (tid < 64) rows[tid] = g_perm[(t << 6) + tid];
    __syncthreads();
    int tx = tid & 15, ty = tid >> 4;
    float acc[4][4] = {};
    for (int k0 = 0; k0 < HIDX; k0 += 16) {
        int mm = tid >> 2, k4 = (tid & 3) << 2;
        int r = rows[mm];
        float4 va = make_float4(0.f, 0.f, 0.f, 0.f);
        if (r >= 0) va = *(const float4*)(x + (size_t)r * HIDX + k0 + k4);
        As[k4 + 0][mm] = va.x; As[k4 + 1][mm] = va.y;
        As[k4 + 2][mm] = va.z; As[k4 + 3][mm] = va.w;
        int kk = tid >> 4, nn = (tid & 15) << 2;
        float4 vb = *(const float4*)(B + (size_t)(k0 + kk) * FFN + col0 + nn);
        Bs[kk][nn] = vb.x; Bs[kk][nn + 1] = vb.y;
        Bs[kk][nn + 2] = vb.z; Bs[kk][nn + 3] = vb.w;
        __syncthreads();
#pragma unroll
        for (int kk2 = 0; kk2 < 16; kk2++) {
            float av[4], bv[4];
#pragma unroll
            for (int i = 0; i < 4; i++) av[i] = As[kk2][ty * 4 + i];
#pragma unroll
            for (int j = 0; j < 4; j++) bv[j] = Bs[kk2][tx * 4 + j];
#pragma unroll
            for (int i = 0; i < 4; i++)
#pragma unroll
                for (int j = 0; j < 4; j++)
                    acc[i][j] = fmaf(av[i], bv[j], acc[i][j]);
        }
        __syncthreads();
    }
#pragma unroll
    for (int i = 0; i < 4; i++) {
#pragma unroll
        for (int j = 0; j < 4; j++) {
            int c = col0 + tx * 4 + j;
            float vv = acc[i][j] + bias[c];
            vv = fmaxf(vv, 0.f);
            g_h[(size_t)((t << 6) + ty * 4 + i) * FFN + c] = vv;
        }
    }
}

__global__ void __launch_bounds__(256) moe_gemm2(
    const float* __restrict__ w2, const float* __restrict__ b2)
{
    int t = blockIdx.y;
    int e = g_texp[t];
    if (e < 0) return;
    const float* B = w2 + (size_t)e * FFN * HIDX;
    const float* bias = b2 + (size_t)e * HIDX;
    int col0 = blockIdx.x << 6;
    __shared__ float As[16][68];
    __shared__ float Bs[16][68];
    __shared__ int rows[64];
    int tid = threadIdx.x;
    if (tid < 64) rows[tid] = g_perm[(t << 6) + tid];
    __syncthreads();
    int tx = tid & 15, ty = tid >> 4;
    float acc[4][4] = {};
    for (int k0 = 0; k0 < FFN; k0 += 16) {
        int mm = tid >> 2, k4 = (tid & 3) << 2;
        float4 va = *(const float4*)(&g_h[(size_t)((t << 6) + mm) * FFN + k0 + k4]);
        As[k4 + 0][mm] = va.x; As[k4 + 1][mm] = va.y;
        As[k4 + 2][mm] = va.z; As[k4 + 3][mm] = va.w;
        int kk = tid >> 4, nn = (tid & 15) << 2;
        float4 vb = *(const float4*)(B + (size_t)(k0 + kk) * HIDX + col0 + nn);
        Bs[kk][nn] = vb.x; Bs[kk][nn + 1] = vb.y;
        Bs[kk][nn + 2] = vb.z; Bs[kk][nn + 3] = vb.w;
        __syncthreads();
#pragma unroll
        for (int kk2 = 0; kk2 < 16; kk2++) {
            float av[4], bv[4];
#pragma unroll
            for (int i = 0; i < 4; i++) av[i] = As[kk2][ty * 4 + i];
#pragma unroll
            for (int j = 0; j < 4; j++) bv[j] = Bs[kk2][tx * 4 + j];
#pragma unroll
            for (int i = 0; i < 4; i++)
#pragma unroll
                for (int j = 0; j < 4; j++)
                    acc[i][j] = fmaf(av[i], bv[j], acc[i][j]);
        }
        __syncthreads();
    }
#pragma unroll
    for (int i = 0; i < 4; i++) {
        int r = rows[ty * 4 + i];
        if (r < 0) continue;
        float ws = g_wsel[r];
#pragma unroll
        for (int j = 0; j < 4; j++) {
            int c = col0 + tx * 4 + j;
            g_y[(size_t)r * HIDX + c] = (acc[i][j] + bias[c]) * ws;
        }
    }
}

__global__ void __launch_bounds__(256) copy_kernel(float* __restrict__ dst,
                                                   const float* __restrict__ src, int n)
{
    int i = blockIdx.x * 256 + threadIdx.x;
    if (i < n) dst[i] = src[i];
}

// ---------------------------------------------------------------------------
extern "C" void kernel_launch(void* const* d_in, const int* in_sizes, int n_in,
                              void* d_out, int out_size)
{
    const float* x_in = (const float*)d_in[0];
    const float* enc  = (const float*)d_in[1];
    const float* wq = (const float*)d_in[2];
    const float* bq = (const float*)d_in[3];
    const float* wk = (const float*)d_in[4];
    const float* bk = (const float*)d_in[5];
    const float* wv = (const float*)d_in[6];
    const float* bv = (const float*)d_in[7];
    const float* wo = (const float*)d_in[8];
    const float* bo = (const float*)d_in[9];
    const float* gw = (const float*)d_in[10];
    const float* gb = (const float*)d_in[11];
    const float* w1 = (const float*)d_in[12];
    const float* b1 = (const float*)d_in[13];
    const float* w2 = (const float*)d_in[14];
    const float* b2 = (const float*)d_in[15];
    const float* lng = (const float*)d_in[16];
    const float* lnb = (const float*)d_in[17];
    float* out = (float*)d_out;

    cudaFuncSetAttribute(bgemm, cudaFuncAttributeMaxDynamicSharedMemorySize, SMEMSZ);

    float *v, *sc, *t1, *xb, *yb;
    uint32_t *qh, *ql, *kh, *kl, *vph, *vpl, *o2h, *o2l, *ath, *atl;
    uint32_t *xph, *xpl, *eph, *epl;
    uint32_t *wqh, *wql, *wkh, *wkl, *wvh, *wvl, *woh, *wol;
    cudaGetSymbolAddress((void**)&v,   g_v);
    cudaGetSymbolAddress((void**)&sc,  g_sc);
    cudaGetSymbolAddress((void**)&t1,  g_t1);
    cudaGetSymbolAddress((void**)&xb,  g_x);
    cudaGetSymbolAddress((void**)&yb,  g_y);
    cudaGetSymbolAddress((void**)&qh,  g_qh);  cudaGetSymbolAddress((void**)&ql, g_ql);
    cudaGetSymbolAddress((void**)&kh,  g_kh);  cudaGetSymbolAddress((void**)&kl, g_kl);
    cudaGetSymbolAddress((void**)&vph, g_vph); cudaGetSymbolAddress((void**)&vpl, g_vpl);
    cudaGetSymbolAddress((void**)&o2h, g_o2h); cudaGetSymbolAddress((void**)&o2l, g_o2l);
    cudaGetSymbolAddress((void**)&ath, g_ath); cudaGetSymbolAddress((void**)&atl, g_atl);
    cudaGetSymbolAddress((void**)&xph, g_xph); cudaGetSymbolAddress((void**)&xpl, g_xpl);
    cudaGetSymbolAddress((void**)&eph, g_eph); cudaGetSymbolAddress((void**)&epl, g_epl);
    cudaGetSymbolAddress((void**)&wqh, g_wqh); cudaGetSymbolAddress((void**)&wql, g_wql);
    cudaGetSymbolAddress((void**)&wkh, g_wkh); cudaGetSymbolAddress((void**)&wkl, g_wkl);
    cudaGetSymbolAddress((void**)&wvh, g_wvh); cudaGetSymbolAddress((void**)&wvl, g_wvl);
    cudaGetSymbolAddress((void**)&woh, g_woh); cudaGetSymbolAddress((void**)&wol, g_wol);

    // one-time packing
    int nWqkv = NL * 2 * (HIDX / 2) * HH;
    packcols<<<nWqkv / 256, 256>>>(wq, wqh, wql, 12);
    packcols<<<nWqkv / 256, 256>>>(wk, wkh, wkl, 12);
    packcols<<<nWqkv / 256, 256>>>(wv, wvh, wvl, 12);
    packcols<<<NL * 2 * (HH / 2) * HIDX / 256, 256>>>(wo, woh, wol, 9);
    packrows<<<TOK * HIDX / 2 / 256, 256>>>(enc, eph, epl);
    packrows<<<TOK * HIDX / 2 / 256, 256>>>(x_in, xph, xpl);
    copy_kernel<<<TOK * HIDX / 256, 256>>>(xb, x_in, TOK * HIDX);

    for (int l = 0; l < NL; l++) {
        for (int a = 0; a < 2; a++) {
            const uint32_t* aAh = a ? eph : xph;
            const uint32_t* aAl = a ? epl : xpl;
            size_t wP = (size_t)(l * 2 + a) * 1048576;
            size_t bOffH = (size_t)(l * 2 + a) * HH;
            int msk = (a == 0);

            bgemm<<<dim3(64, 32, 1), 256, SMEMSZ>>>(
                aAh, aAl, 256, 0, 0, wqh + wP, wql + wP, HH, 0, 0,
                nullptr, 0, 0, 0, qh, ql, 2048, 0, 0,
                bq + bOffH, HIDX, 0, 0, 0);
            bgemm<<<dim3(64, 32, 1), 256, SMEMSZ>>>(
                aAh, aAl, 256, 0, 0, wkh + wP, wkl + wP, HH, 0, 0,
                nullptr, 0, 0, 0, kh, kl, 2048, 0, 0,
                bk + bOffH, HIDX, 0, 0, 0);
            bgemm<<<dim3(64, 32, 1), 256, SMEMSZ>>>(
                xph, xpl, 256, 0, 0, wvh + wP, wvl + wP, HH, 0, 0,
                v, HH, 0, 0, nullptr, nullptr, 0, 0, 0,
                bv + bOffH, HIDX, 0, 0, 0);
            packv<<<NB * NH * (SEQ / 2) * HIDX / 256, 256>>>(v, vph, vpl);

            bgemm<<<dim3(16, 8, 32), 256, SMEMSZ>>>(
                qh, ql, 256, 2097152, 262144, kh, kl, 256, 2097152, 262144,
                sc, SEQ, 8388608, 1048576, nullptr, nullptr, 0, 0, 0,
                nullptr, HIDX, 1, msk, 0);
            softmax_kernel<<<NB * NH * SEQ, 256>>>(sc, ath, atl, msk);

            bgemm<<<dim3(8, 8, 32), 256, SMEMSZ>>>(
                ath, atl, 512, 4194304, 524288, vph, vpl, 512, 2097152, 262144,
                nullptr, 0, 0, 0, o2h, o2l, 2048, 2097152, 256,
                nullptr, SEQ, 0, 0, msk);

            bgemm<<<dim3(8, 32, 1), 256, SMEMSZ>>>(
                o2h, o2l, 2048, 0, 0, woh + wP, wol + wP, HIDX, 0, 0,
                t1, HIDX, 0, 0, nullptr, nullptr, 0, 0, 0,
                bo + (size_t)(l * 2 + a) * HIDX, HH, 0, 0, 0);

            ln_kernel<<<TOK, 256>>>(t1, xb, lng + (size_t)(l * 3 + a) * HIDX,
                                    lnb + (size_t)(l * 3 + a) * HIDX, xb, xph, xpl);
        }
        gate_kernel<<<TOK / 8, 256>>>(xb, gw + (size_t)l * HIDX * NE, gb + (size_t)l * NE);
        moe_setup<<<1, 256>>>();
        moe_gemm1<<<dim3(FFN / 64, MAXT), 256>>>(xb, w1 + (size_t)l * NE * HIDX * FFN,
                                                 b1 + (size_t)l * NE * FFN);
        moe_gemm2<<<dim3(HIDX / 64, MAXT), 256>>>(w2 + (size_t)l * NE * FFN * HIDX,
                                                  b2 + (size_t)l * NE * HIDX);
        float* lnOut = (l == NL - 1) ? out : xb;
        ln_kernel<<<TOK, 256>>>(yb, xb, lng + (size_t)(l * 3 + 2) * HIDX,
                                lnb + (size_t)(l * 3 + 2) * HIDX, lnOut, xph, xpl);
    }
}

// round 13
// speedup vs baseline: 1.0057x; 1.0057x over previous
#include <cuda_runtime.h>
#include <cuda_bf16.h>
#include <cstdint>

#define NL 2
#define NH 8
#define SEQ 1024
#define HIDX 512
#define HH 4096
#define NE 8
#define FFN 1024
#define NB 4
#define TOK 4096
#define EPSV 1e-5f
#define MAXROWS 4608
#define MAXT 72
#define SMEMSZ 55296
#define NQKV 12288

// fp32 buffers
static __device__ float g_sc[(size_t)NB * NH * SEQ * SEQ];
static __device__ float g_t1[(size_t)TOK * HIDX];
static __device__ float g_x[(size_t)TOK * HIDX];
static __device__ float g_y[(size_t)TOK * HIDX];
static __device__ float g_h[(size_t)MAXROWS * FFN];
static __device__ float g_bcat[NL * 2 * NQKV];
static __device__ int   g_sel[TOK];
static __device__ float g_wsel[TOK];
static __device__ int   g_perm[MAXROWS];
static __device__ int   g_texp[MAXT];

// packed bf16-pair buffers (hi/lo), 16B aligned for cp.async
#define PKA __device__ __align__(16)
static PKA uint32_t g_qh[(size_t)TOK * HH / 2], g_ql[(size_t)TOK * HH / 2];
static PKA uint32_t g_kh[(size_t)TOK * HH / 2], g_kl[(size_t)TOK * HH / 2];
static PKA uint32_t g_vdh[(size_t)TOK * HH / 2], g_vdl[(size_t)TOK * HH / 2];
static PKA uint32_t g_vph[(size_t)NB * NH * (SEQ / 2) * HIDX], g_vpl[(size_t)NB * NH * (SEQ / 2) * HIDX];
static PKA uint32_t g_o2h[(size_t)TOK * HH / 2], g_o2l[(size_t)TOK * HH / 2];
static PKA uint32_t g_ath[(size_t)NB * NH * SEQ * SEQ / 2], g_atl[(size_t)NB * NH * SEQ * SEQ / 2];
static PKA uint32_t g_xph[TOK * HIDX / 2], g_xpl[TOK * HIDX / 2];
static PKA uint32_t g_eph[TOK * HIDX / 2], g_epl[TOK * HIDX / 2];
// fused QKV weights: [slab][256 kp][12288]
static PKA uint32_t g_wah[(size_t)NL * 2 * (HIDX / 2) * NQKV], g_wal[(size_t)NL * 2 * (HIDX / 2) * NQKV];
static PKA uint32_t g_woh[(size_t)NL * 2 * HH / 2 * HIDX], g_wol[(size_t)NL * 2 * HH / 2 * HIDX];

__device__ __forceinline__ void split2(float x, float y, uint32_t& hi, uint32_t& lo)
{
    __nv_bfloat162 h = __floats2bfloat162_rn(x, y);
    float2 hf = __bfloat1622float2(h);
    __nv_bfloat162 l = __floats2bfloat162_rn(x - hf.x, y - hf.y);
    hi = *(uint32_t*)&h;
    lo = *(uint32_t*)&l;
}

#define MMA_BF16(d, a, b)                                                     \
    asm volatile(                                                             \
        "mma.sync.aligned.m16n8k16.row.col.f32.bf16.bf16.f32 "                \
        "{%0,%1,%2,%3},{%4,%5,%6,%7},{%8,%9},{%0,%1,%2,%3};"                  \
        : "+f"(d[0]), "+f"(d[1]), "+f"(d[2]), "+f"(d[3])                      \
        : "r"(a[0]), "r"(a[1]), "r"(a[2]), "r"(a[3]), "r"(b[0]), "r"(b[1]))

// ---------------------------------------------------------------------------
// Packed split-bf16 mma.sync GEMM (round-6 proven inner loop, untouched).
// Epilogue addition: when col0>=4096 the packed store redirects to Cph2/Cph3
// (component select for the fused QKV launch; never triggers when N<=1024).
// ---------------------------------------------------------------------------
__global__ void __launch_bounds__(256) bgemm(
    const uint32_t* __restrict__ Ah, const uint32_t* __restrict__ Al,
    int ldaP, long long aSb, long long aSh,
    const uint32_t* __restrict__ Bh, const uint32_t* __restrict__ Bl,
    int ldbB, long long bSb, long long bSh,
    float* __restrict__ C, int ldc, long long cSb, long long cSh,
    uint32_t* __restrict__ Cph, uint32_t* __restrict__ Cpl,
    uint32_t* __restrict__ Cph2, uint32_t* __restrict__ Cpl2,
    uint32_t* __restrict__ Cph3, uint32_t* __restrict__ Cpl3,
    int ldcP, long long cpSb, long long cpSh,
    const float* __restrict__ bias,
    int K, int transB, int causalSkip, int causalK)
{
    int row0 = blockIdx.y * 128;
    int col0 = blockIdx.x * 64;
    if (causalSkip && col0 >= row0 + 128) return;
    long long zb = blockIdx.z >> 3, zh = blockIdx.z & 7;
    Ah += zb * aSb + zh * aSh;
    Al += zb * aSb + zh * aSh;
    Bh += zb * bSb + zh * bSh;
    Bl += zb * bSb + zh * bSh;

    extern __shared__ uint32_t sm[];
    uint32_t smBase = (uint32_t)__cvta_generic_to_shared(sm);

    int tid = threadIdx.x;
    int warp = tid >> 5, lane = tid & 31;
    int wm0 = (warp >> 1) << 5;
    int wn0 = (warp & 1) << 5;
    int tg = lane & 3, gp = lane >> 2;

    const uint32_t* pAh = Ah + (long long)(row0 + (tid >> 1)) * ldaP + ((tid & 1) << 2);
    const uint32_t* pAl = Al + (long long)(row0 + (tid >> 1)) * ldaP + ((tid & 1) << 2);
    int aOff = (tid >> 1) * 12 + ((tid & 1) << 2);

    const uint32_t* pB;
    int bOff;
    int bBase = (tid < 128) ? 9216 : 11520;
    int tt = tid & 127;
    long long bStep;
    if (!transB) {
        int kp = tt >> 4, cc = (tt & 15) << 2;
        pB = (tid < 128 ? Bh : Bl) + (long long)kp * ldbB + col0 + cc;
        bOff = kp * 72 + cc;
        bStep = ldbB;
    } else {
        int nn = tt >> 1, cc = (tt & 1) << 2;
        pB = (tid < 128 ? Bh : Bl) + (long long)(col0 + nn) * ldbB + cc;
        bOff = nn * 12 + cc;
        bStep = 1;
    }

#define CPA(doff, src)                                                        \
    asm volatile("cp.async.cg.shared.global [%0], [%1], 16;"                  \
                 :: "r"(smBase + ((doff) << 2)), "l"(src))
#define ISSUE(st, kp0)                                                        \
    do {                                                                      \
        CPA((st) * 1536 + aOff, pAh + (kp0));                                 \
        CPA(4608 + (st) * 1536 + aOff, pAl + (kp0));                          \
        CPA(bBase + (st) * 768 + bOff, pB + (long long)(kp0) * bStep);        \
    } while (0)
#define COMMIT asm volatile("cp.async.commit_group;" ::)

    int kend = causalK ? (row0 + 128) : K;
    int niter = kend >> 4;

    ISSUE(0, 0);
    COMMIT;
    if (niter > 1) ISSUE(1, 8);
    COMMIT;

    float acc[2][4][4];
#pragma unroll
    for (int i = 0; i < 2; i++)
#pragma unroll
        for (int j = 0; j < 4; j++)
#pragma unroll
            for (int t = 0; t < 4; t++) acc[i][j][t] = 0.f;

    for (int i = 0; i < niter; i++) {
        if (i + 1 < niter) asm volatile("cp.async.wait_group 1;" ::);
        else               asm volatile("cp.async.wait_group 0;" ::);
        __syncthreads();
        if (i + 2 < niter) {
            int s2 = (i + 2) % 3;
            ISSUE(s2, (i + 2) * 8);
        }
        COMMIT;

        int s = i % 3;
        const uint32_t* aHs = sm + s * 1536;
        const uint32_t* aLs = sm + 4608 + s * 1536;
        const uint32_t* bHs = sm + 9216 + s * 768;
        const uint32_t* bLs = sm + 11520 + s * 768;

        uint32_t aF[2][4], aG[2][4], bF[4][2], bG[4][2];
#pragma unroll
        for (int mt = 0; mt < 2; mt++) {
            int m = wm0 + mt * 16 + gp;
            aF[mt][0] = aHs[m * 12 + tg];
            aF[mt][1] = aHs[(m + 8) * 12 + tg];
            aF[mt][2] = aHs[m * 12 + tg + 4];
            aF[mt][3] = aHs[(m + 8) * 12 + tg + 4];
            aG[mt][0] = aLs[m * 12 + tg];
            aG[mt][1] = aLs[(m + 8) * 12 + tg];
            aG[mt][2] = aLs[m * 12 + tg + 4];
            aG[mt][3] = aLs[(m + 8) * 12 + tg + 4];
        }
        if (!transB) {
#pragma unroll
            for (int nt = 0; nt < 4; nt++) {
                int n = wn0 + nt * 8 + gp;
                bF[nt][0] = bHs[tg * 72 + n];
                bF[nt][1] = bHs[(tg + 4) * 72 + n];
                bG[nt][0] = bLs[tg * 72 + n];
                bG[nt][1] = bLs[(tg + 4) * 72 + n];
            }
        } else {
#pragma unroll
            for (int nt = 0; nt < 4; nt++) {
                int n = wn0 + nt * 8 + gp;
                bF[nt][0] = bHs[n * 12 + tg];
                bF[nt][1] = bHs[n * 12 + tg + 4];
                bG[nt][0] = bLs[n * 12 + tg];
                bG[nt][1] = bLs[n * 12 + tg + 4];
            }
        }
#pragma unroll
        for (int mt = 0; mt < 2; mt++)
#pragma unroll
            for (int nt = 0; nt < 4; nt++) {
                MMA_BF16(acc[mt][nt], aF[mt], bF[nt]);
                MMA_BF16(acc[mt][nt], aF[mt], bG[nt]);
                MMA_BF16(acc[mt][nt], aG[mt], bF[nt]);
            }
    }

    if (Cph) {
        uint32_t* oph = Cph;
        uint32_t* opl = Cpl;
        int cbase = 0;
        if (Cph3 && col0 >= 8192)      { oph = Cph3; opl = Cpl3; cbase = 8192; }
        else if (Cph2 && col0 >= 4096) { oph = Cph2; opl = Cpl2; cbase = 4096; }
        oph += zb * cpSb + zh * cpSh;
        opl += zb * cpSb + zh * cpSh;
#pragma unroll
        for (int mt = 0; mt < 2; mt++) {
            long long r = row0 + wm0 + mt * 16 + gp;
#pragma unroll
            for (int nt = 0; nt < 4; nt++) {
                int c = col0 + wn0 + nt * 8 + tg * 2;
                float b0 = bias ? bias[c] : 0.f;
                float b1 = bias ? bias[c + 1] : 0.f;
                int cp = (c - cbase) >> 1;
                uint32_t h, l;
                split2(acc[mt][nt][0] + b0, acc[mt][nt][1] + b1, h, l);
                oph[r * ldcP + cp] = h;
                opl[r * ldcP + cp] = l;
                split2(acc[mt][nt][2] + b0, acc[mt][nt][3] + b1, h, l);
                oph[(r + 8) * ldcP + cp] = h;
                opl[(r + 8) * ldcP + cp] = l;
            }
        }
    } else {
        C += zb * cSb + zh * cSh;
#pragma unroll
        for (int mt = 0; mt < 2; mt++) {
            long long r = row0 + wm0 + mt * 16 + gp;
#pragma unroll
            for (int nt = 0; nt < 4; nt++) {
                int c = col0 + wn0 + nt * 8 + tg * 2;
                float b0 = bias ? bias[c] : 0.f;
                float b1 = bias ? bias[c + 1] : 0.f;
                float2 lo = make_float2(acc[mt][nt][0] + b0, acc[mt][nt][1] + b1);
                float2 hi = make_float2(acc[mt][nt][2] + b0, acc[mt][nt][3] + b1);
                *(float2*)(C + r * ldc + c) = lo;
                *(float2*)(C + (r + 8) * ldc + c) = hi;
            }
        }
    }
#undef CPA
#undef ISSUE
#undef COMMIT
}

// ---------------------------------------------------------------------------
// Pre-split kernels
// ---------------------------------------------------------------------------
__global__ void __launch_bounds__(256) packrows(const float* __restrict__ src,
                                                uint32_t* __restrict__ h, uint32_t* __restrict__ l)
{
    int idx = blockIdx.x * 256 + threadIdx.x;
    float2 v = ((const float2*)src)[idx];
    split2(v.x, v.y, h[idx], l[idx]);
}

__global__ void __launch_bounds__(256) packcols(const float* __restrict__ src,
                                                uint32_t* __restrict__ h, uint32_t* __restrict__ l,
                                                int logN)
{
    int idx = blockIdx.x * 256 + threadIdx.x;
    int kp = idx >> logN;
    int c = idx & ((1 << logN) - 1);
    const float* p = src + (((size_t)kp * 2) << logN) + c;
    split2(p[0], p[1 << logN], h[idx], l[idx]);
}

// fused QKV weight pack: out[slab][kp][12288] = pairs along K of wq|wk|wv cols
__global__ void __launch_bounds__(256) packqkv(const float* __restrict__ wq,
                                               const float* __restrict__ wk,
                                               const float* __restrict__ wv,
                                               uint32_t* __restrict__ h,
                                               uint32_t* __restrict__ l)
{
    int idx = blockIdx.x * 256 + threadIdx.x;
    int slab = idx / (256 * NQKV);
    int rem = idx - slab * (256 * NQKV);
    int kp = rem / NQKV;
    int c = rem - kp * NQKV;
    int comp = c >> 12;
    int c2 = c & 4095;
    const float* W = (comp == 0) ? wq : (comp == 1) ? wk : wv;
    W += (size_t)slab * HIDX * HH;
    float a = W[(size_t)(2 * kp) * HH + c2];
    float b = W[(size_t)(2 * kp + 1) * HH + c2];
    split2(a, b, h[idx], l[idx]);
}

__global__ void __launch_bounds__(256) packbias(const float* __restrict__ bq,
                                                const float* __restrict__ bk,
                                                const float* __restrict__ bv,
                                                float* __restrict__ bcat)
{
    int idx = blockIdx.x * 256 + threadIdx.x;
    int slab = idx / NQKV;
    int c = idx - slab * NQKV;
    int comp = c >> 12;
    int c2 = c & 4095;
    const float* src = (comp == 0) ? bq : (comp == 1) ? bk : bv;
    bcat[idx] = src[slab * HH + c2];
}

// reconstruct fp32 V element at flat quirk index f from packed d-pair buffers
__device__ __forceinline__ float vread(const uint32_t* __restrict__ vh,
                                       const uint32_t* __restrict__ vl, size_t f)
{
    size_t p = (f >> 12) * 2048 + ((f & 4095) >> 1);
    __nv_bfloat162 h = *(const __nv_bfloat162*)&vh[p];
    __nv_bfloat162 l = *(const __nv_bfloat162*)&vl[p];
    float2 hf = __bfloat1622float2(h);
    float2 lf = __bfloat1622float2(l);
    return (f & 1) ? (hf.y + lf.y) : (hf.x + lf.x);
}

// V packed d-pairs -> packed [b][h][jp][d] (pairs along seq j)
__global__ void __launch_bounds__(256) packv(const uint32_t* __restrict__ vh,
                                             const uint32_t* __restrict__ vl,
                                             uint32_t* __restrict__ h, uint32_t* __restrict__ l)
{
    int idx = blockIdx.x * 256 + threadIdx.x;
    int b  = idx >> 21;
    int hh = (idx >> 18) & 7;
    int jp = (idx >> 9) & 511;
    int d  = idx & 511;
    size_t f = (size_t)b * 4194304 + (size_t)hh * 524288 + (size_t)jp * 1024 + d;
    split2(vread(vh, vl, f), vread(vh, vl, f + 512), h[idx], l[idx]);
}

// ---------------------------------------------------------------------------
// Softmax over rows of SEQ; writes packed bf16 hi/lo probabilities.
// ---------------------------------------------------------------------------
__global__ void __launch_bounds__(256) softmax_kernel(const float* __restrict__ sc,
                                                      uint32_t* __restrict__ ath,
                                                      uint32_t* __restrict__ atl, int masked)
{
    long long base = (long long)blockIdx.x * SEQ;
    long long pbase = (long long)blockIdx.x * (SEQ / 2);
    int i = blockIdx.x & (SEQ - 1);
    int n = masked ? (i + 1) : SEQ;
    int tid = threadIdx.x;
    __shared__ float red[8];

    float v[2][2];
    float mx = -1e30f;
#pragma unroll
    for (int j = 0; j < 2; j++) {
        int c = (tid + (j << 8)) << 1;
        float2 t = *(const float2*)(sc + base + c);
        v[j][0] = (c < n) ? t.x : -1e30f;
        v[j][1] = (c + 1 < n) ? t.y : -1e30f;
        mx = fmaxf(mx, fmaxf(v[j][0], v[j][1]));
    }
#pragma unroll
    for (int o = 16; o; o >>= 1) mx = fmaxf(mx, __shfl_xor_sync(0xffffffffu, mx, o));
    if ((tid & 31) == 0) red[tid >> 5] = mx;
    __syncthreads();
    mx = red[0];
#pragma unroll
    for (int w = 1; w < 8; w++) mx = fmaxf(mx, red[w]);
    __syncthreads();

    float s = 0.f;
#pragma unroll
    for (int j = 0; j < 2; j++) {
        int c = (tid + (j << 8)) << 1;
        v[j][0] = (c < n) ? __expf(v[j][0] - mx) : 0.f;
        v[j][1] = (c + 1 < n) ? __expf(v[j][1] - mx) : 0.f;
        s += v[j][0] + v[j][1];
    }
#pragma unroll
    for (int o = 16; o; o >>= 1) s += __shfl_xor_sync(0xffffffffu, s, o);
    if ((tid & 31) == 0) red[tid >> 5] = s;
    __syncthreads();
    s = 0.f;
#pragma unroll
    for (int w = 0; w < 8; w++) s += red[w];
    float inv = 1.f / s;
#pragma unroll
    for (int j = 0; j < 2; j++) {
        uint32_t h, l;
        split2(v[j][0] * inv, v[j][1] * inv, h, l);
        ath[pbase + tid + (j << 8)] = h;
        atl[pbase + tid + (j << 8)] = l;
    }
}

// ---------------------------------------------------------------------------
// y = LayerNorm(a + r); also writes packed bf16 hi/lo of y.
// ---------------------------------------------------------------------------
__global__ void __launch_bounds__(256) ln_kernel(
    const float* __restrict__ a, const float* __restrict__ r,
    const float* __restrict__ g, const float* __restrict__ b,
    float* __restrict__ y, uint32_t* __restrict__ yph, uint32_t* __restrict__ ypl)
{
    long long base = (long long)blockIdx.x * HIDX;
    int tid = threadIdx.x;
    int c = tid << 1;
    __shared__ float red[8];

    float2 av = *(const float2*)(a + base + c);
    float2 rv = *(const float2*)(r + base + c);
    float z0 = av.x + rv.x, z1 = av.y + rv.y;
    float s = z0 + z1;
#pragma unroll
    for (int o = 16; o; o >>= 1) s += __shfl_xor_sync(0xffffffffu, s, o);
    if ((tid & 31) == 0) red[tid >> 5] = s;
    __syncthreads();
    s = 0.f;
#pragma unroll
    for (int w = 0; w < 8; w++) s += red[w];
    float m = s * (1.f / HIDX);
    float d0 = z0 - m, d1 = z1 - m;
    float qs = d0 * d0 + d1 * d1;
    __syncthreads();
#pragma unroll
    for (int o = 16; o; o >>= 1) qs += __shfl_xor_sync(0xffffffffu, qs, o);
    if ((tid & 31) == 0) red[tid >> 5] = qs;
    __syncthreads();
    qs = 0.f;
#pragma unroll
    for (int w = 0; w < 8; w++) qs += red[w];
    float inv = rsqrtf(qs * (1.f / HIDX) + EPSV);
    float2 gg = *(const float2*)(g + c);
    float2 bb = *(const float2*)(b + c);
    float o0 = gg.x * d0 * inv + bb.x;
    float o1 = gg.y * d1 * inv + bb.y;
    *(float2*)(y + base + c) = make_float2(o0, o1);
    uint32_t h, l;
    split2(o0, o1, h, l);
    yph[(long long)blockIdx.x * 256 + tid] = h;
    ypl[(long long)blockIdx.x * 256 + tid] = l;
}

// ---------------------------------------------------------------------------
// Gate: softmax over E=8, pick 2nd-largest (faithful TOPK-1 bug).
// ---------------------------------------------------------------------------
__global__ void __launch_bounds__(256) gate_kernel(
    const float* __restrict__ x, const float* __restrict__ gw, const float* __restrict__ gb)
{
    int tok = (blockIdx.x << 3) + (threadIdx.x >> 5);
    int lane = threadIdx.x & 31;
    const float* xr = x + (size_t)tok * HIDX;
    float acc[8] = {0, 0, 0, 0, 0, 0, 0, 0};
    for (int j = lane; j < HIDX; j += 32) {
        float xv = xr[j];
        float4 a0 = *(const float4*)(gw + j * 8);
        float4 a1 = *(const float4*)(gw + j * 8 + 4);
        acc[0] += xv * a0.x; acc[1] += xv * a0.y; acc[2] += xv * a0.z; acc[3] += xv * a0.w;
        acc[4] += xv * a1.x; acc[5] += xv * a1.y; acc[6] += xv * a1.z; acc[7] += xv * a1.w;
    }
#pragma unroll
    for (int e = 0; e < 8; e++)
#pragma unroll
        for (int o = 16; o; o >>= 1) acc[e] += __shfl_xor_sync(0xffffffffu, acc[e], o);
    if (lane == 0) {
        float mx = -1e30f;
#pragma unroll
        for (int e = 0; e < 8; e++) { acc[e] += gb[e]; mx = fmaxf(mx, acc[e]); }
        float p[8];
#pragma unroll
        for (int e = 0; e < 8; e++) p[e] = __expf(acc[e] - mx);
        float v1 = -1.f, v2 = -1.f; int i1 = 0, i2 = 0;
#pragma unroll
        for (int e = 0; e < 8; e++) {
            if (p[e] > v1)      { v2 = v1; i2 = i1; v1 = p[e]; i1 = e; }
            else if (p[e] > v2) { v2 = p[e]; i2 = e; }
        }
        g_sel[tok] = i2;
        g_wsel[tok] = v2 / (v1 + v2);
    }
}

__global__ void __launch_bounds__(256) moe_setup()
{
    __shared__ int cnt[8], cursor[8];
    int tid = threadIdx.x;
    if (tid < 8) cnt[tid] = 0;
    for (int i = tid; i < MAXROWS; i += 256) g_perm[i] = -1;
    __syncthreads();
    for (int i = tid; i < TOK; i += 256) atomicAdd(&cnt[g_sel[i]], 1);
    __syncthreads();
    if (tid == 0) {
        int base = 0, t = 0;
        for (int e = 0; e < 8; e++) {
            cursor[e] = base;
            int tiles = (cnt[e] + 63) >> 6;
            for (int j = 0; j < tiles; j++) g_texp[t++] = e;
            base += tiles << 6;
        }
        for (; t < MAXT; t++) g_texp[t] = -1;
    }
    __syncthreads();
    for (int i = tid; i < TOK; i += 256) {
        int e = g_sel[i];
        int p = atomicAdd(&cursor[e], 1);
        g_perm[p] = i;
    }
}

__global__ void __launch_bounds__(256) moe_gemm1(
    const float* __restrict__ x, const float* __restrict__ w1, const float* __restrict__ b1)
{
    int t = blockIdx.y;
    int e = g_texp[t];
    if (e < 0) return;
    const float* B = w1 + (size_t)e * HIDX * FFN;
    const float* bias = b1 + (size_t)e * FFN;
    int col0 = blockIdx.x << 6;
    __shared__ float As[16][68];
    __shared__ float Bs[16][68];
    __shared__ int rows[64];
    int tid = threadIdx.x;
    if (tid < 64) rows[tid] = g_perm[(t << 6) + tid];
    __syncthreads();
    int tx = tid & 15, ty = tid >> 4;
    float acc[4][4] = {};
    for (int k0 = 0; k0 < HIDX; k0 += 16) {
        int mm = tid >> 2, k4 = (tid & 3) << 2;
        int r = rows[mm];
        float4 va = make_float4(0.f, 0.f, 0.f, 0.f);
        if (r >= 0) va = *(const float4*)(x + (size_t)r * HIDX + k0 + k4);
        As[k4 + 0][mm] = va.x; As[k4 + 1][mm] = va.y;
        As[k4 + 2][mm] = va.z; As[k4 + 3][mm] = va.w;
        int kk = tid >> 4, nn = (tid & 15) << 2;
        float4 vb = *(const float4*)(B + (size_t)(k0 + kk) * FFN + col0 + nn);
        Bs[kk][nn] = vb.x; Bs[kk][nn + 1] = vb.y;
        Bs[kk][nn + 2] = vb.z; Bs[kk][nn + 3] = vb.w;
        __syncthreads();
#pragma unroll
        for (int kk2 = 0; kk2 < 16; kk2++) {
            float av[4], bv[4];
#pragma unroll
            for (int i = 0; i < 4; i++) av[i] = As[kk2][ty * 4 + i];
#pragma unroll
            for (int j = 0; j < 4; j++) bv[j] = Bs[kk2][tx * 4 + j];
#pragma unroll
            for (int i = 0; i < 4; i++)
#pragma unroll
                for (int j = 0; j < 4; j++)
                    acc[i][j] = fmaf(av[i], bv[j], acc[i][j]);
        }
        __syncthreads();
    }
#pragma unroll
    for (int i = 0; i < 4; i++) {
#pragma unroll
        for (int j = 0; j < 4; j++) {
            int c = col0 + tx * 4 + j;
            float vv = acc[i][j] + bias[c];
            vv = fmaxf(vv, 0.f);
            g_h[(size_t)((t << 6) + ty * 4 + i) * FFN + c] = vv;
        }
    }
}

__global__ void __launch_bounds__(256) moe_gemm2(
    const float* __restrict__ w2, const float* __restrict__ b2)
{
    int t = blockIdx.y;
    int e = g_texp[t];
    if (e < 0) return;
    const float* B = w2 + (size_t)e * FFN * HIDX;
    const float* bias = b2 + (size_t)e * HIDX;
    int col0 = blockIdx.x << 6;
    __shared__ float As[16][68];
    __shared__ float Bs[16][68];
    __shared__ int rows[64];
    int tid = threadIdx.x;
    if (tid < 64) rows[tid] = g_perm[(t << 6) + tid];
    __syncthreads();
    int tx = tid & 15, ty = tid >> 4;
    float acc[4][4] = {};
    for (int k0 = 0; k0 < FFN; k0 += 16) {
        int mm = tid >> 2, k4 = (tid & 3) << 2;
        float4 va = *(const float4*)(&g_h[(size_t)((t << 6) + mm) * FFN + k0 + k4]);
        As[k4 + 0][mm] = va.x; As[k4 + 1][mm] = va.y;
        As[k4 + 2][mm] = va.z; As[k4 + 3][mm] = va.w;
        int kk = tid >> 4, nn = (tid & 15) << 2;
        float4 vb = *(const float4*)(B + (size_t)(k0 + kk) * HIDX + col0 + nn);
        Bs[kk][nn] = vb.x; Bs[kk][nn + 1] = vb.y;
        Bs[kk][nn + 2] = vb.z; Bs[kk][nn + 3] = vb.w;
        __syncthreads();
#pragma unroll
        for (int kk2 = 0; kk2 < 16; kk2++) {
            float av[4], bv[4];
#pragma unroll
            for (int i = 0; i < 4; i++) av[i] = As[kk2][ty * 4 + i];
#pragma unroll
            for (int j = 0; j < 4; j++) bv[j] = Bs[kk2][tx * 4 + j];
#pragma unroll
            for (int i = 0; i < 4; i++)
#pragma unroll
                for (int j = 0; j < 4; j++)
                    acc[i][j] = fmaf(av[i], bv[j], acc[i][j]);
        }
        __syncthreads();
    }
#pragma unroll
    for (int i = 0; i < 4; i++) {
        int r = rows[ty * 4 + i];
        if (r < 0) continue;
        float ws = g_wsel[r];
#pragma unroll
        for (int j = 0; j < 4; j++) {
            int c = col0 + tx * 4 + j;
            g_y[(size_t)r * HIDX + c] = (acc[i][j] + bias[c]) * ws;
        }
    }
}

__global__ void __launch_bounds__(256) copy_kernel(float* __restrict__ dst,
                                                   const float* __restrict__ src, int n)
{
    int i = blockIdx.x * 256 + threadIdx.x;
    if (i < n) dst[i] = src[i];
}

// ---------------------------------------------------------------------------
extern "C" void kernel_launch(void* const* d_in, const int* in_sizes, int n_in,
                              void* d_out, int out_size)
{
    const float* x_in = (const float*)d_in[0];
    const float* enc  = (const float*)d_in[1];
    const float* wq = (const float*)d_in[2];
    const float* bq = (const float*)d_in[3];
    const float* wk = (const float*)d_in[4];
    const float* bk = (const float*)d_in[5];
    const float* wv = (const float*)d_in[6];
    const float* bv = (const float*)d_in[7];
    const float* wo = (const float*)d_in[8];
    const float* bo = (const float*)d_in[9];
    const float* gw = (const float*)d_in[10];
    const float* gb = (const float*)d_in[11];
    const float* w1 = (const float*)d_in[12];
    const float* b1 = (const float*)d_in[13];
    const float* w2 = (const float*)d_in[14];
    const float* b2 = (const float*)d_in[15];
    const float* lng = (const float*)d_in[16];
    const float* lnb = (const float*)d_in[17];
    float* out = (float*)d_out;

    cudaFuncSetAttribute(bgemm, cudaFuncAttributeMaxDynamicSharedMemorySize, SMEMSZ);

    float *sc, *t1, *xb, *yb, *bcat;
    uint32_t *qh, *ql, *kh, *kl, *vdh, *vdl, *vph, *vpl, *o2h, *o2l, *ath, *atl;
    uint32_t *xph, *xpl, *eph, *epl;
    uint32_t *wah, *wal, *woh, *wol;
    cudaGetSymbolAddress((void**)&sc,  g_sc);
    cudaGetSymbolAddress((void**)&t1,  g_t1);
    cudaGetSymbolAddress((void**)&xb,  g_x);
    cudaGetSymbolAddress((void**)&yb,  g_y);
    cudaGetSymbolAddress((void**)&bcat, g_bcat);
    cudaGetSymbolAddress((void**)&qh,  g_qh);  cudaGetSymbolAddress((void**)&ql, g_ql);
    cudaGetSymbolAddress((void**)&kh,  g_kh);  cudaGetSymbolAddress((void**)&kl, g_kl);
    cudaGetSymbolAddress((void**)&vdh, g_vdh); cudaGetSymbolAddress((void**)&vdl, g_vdl);
    cudaGetSymbolAddress((void**)&vph, g_vph); cudaGetSymbolAddress((void**)&vpl, g_vpl);
    cudaGetSymbolAddress((void**)&o2h, g_o2h); cudaGetSymbolAddress((void**)&o2l, g_o2l);
    cudaGetSymbolAddress((void**)&ath, g_ath); cudaGetSymbolAddress((void**)&atl, g_atl);
    cudaGetSymbolAddress((void**)&xph, g_xph); cudaGetSymbolAddress((void**)&xpl, g_xpl);
    cudaGetSymbolAddress((void**)&eph, g_eph); cudaGetSymbolAddress((void**)&epl, g_epl);
    cudaGetSymbolAddress((void**)&wah, g_wah); cudaGetSymbolAddress((void**)&wal, g_wal);
    cudaGetSymbolAddress((void**)&woh, g_woh); cudaGetSymbolAddress((void**)&wol, g_wol);

    // one-time packing
    packqkv<<<NL * 2 * 256 * NQKV / 256, 256>>>(wq, wk, wv, wah, wal);
    packbias<<<NL * 2 * NQKV / 256, 256>>>(bq, bk, bv, bcat);
    packcols<<<NL * 2 * (HH / 2) * HIDX / 256, 256>>>(wo, woh, wol, 9);
    packrows<<<TOK * HIDX / 2 / 256, 256>>>(enc, eph, epl);
    packrows<<<TOK * HIDX / 2 / 256, 256>>>(x_in, xph, xpl);
    copy_kernel<<<TOK * HIDX / 256, 256>>>(xb, x_in, TOK * HIDX);

    for (int l = 0; l < NL; l++) {
        for (int a = 0; a < 2; a++) {
            const uint32_t* aAh = a ? eph : xph;   // Q/K input (cross: encoder)
            const uint32_t* aAl = a ? epl : xpl;
            size_t wP = (size_t)(l * 2 + a) * 256 * NQKV;
            int msk = (a == 0);

            // fused QKV projection: Q->qh, K->kh, V->vdh via component select.
            // NOTE: Q/K use aAh (enc for cross-attn); V must use xph. Since the
            // reference computes V from x always, launch V separately when the
            // sources differ (cross-attn), else fully fused.
            if (a == 0) {
                bgemm<<<dim3(NQKV / 64, 32, 1), 256, SMEMSZ>>>(
                    xph, xpl, 256, 0, 0, wah + wP, wal + wP, NQKV, 0, 0,
                    nullptr, 0, 0, 0,
                    qh, ql, kh, kl, vdh, vdl, 2048, 0, 0,
                    bcat + (size_t)(l * 2 + a) * NQKV, HIDX, 0, 0, 0);
            } else {
                // Q+K from encoder (first 8192 cols)
                bgemm<<<dim3(8192 / 64, 32, 1), 256, SMEMSZ>>>(
                    aAh, aAl, 256, 0, 0, wah + wP, wal + wP, NQKV, 0, 0,
                    nullptr, 0, 0, 0,
                    qh, ql, kh, kl, nullptr, nullptr, 2048, 0, 0,
                    bcat + (size_t)(l * 2 + a) * NQKV, HIDX, 0, 0, 0);
                // V from x (last 4096 cols) -> redirect base so col0-8192 lands in vdh
                bgemm<<<dim3(4096 / 64, 32, 1), 256, SMEMSZ>>>(
                    xph, xpl, 256, 0, 0, wah + wP + 8192, wal + wP + 8192, NQKV, 0, 0,
                    nullptr, 0, 0, 0,
                    vdh, vdl, nullptr, nullptr, nullptr, nullptr, 2048, 0, 0,
                    bcat + (size_t)(l * 2 + a) * NQKV + 8192, HIDX, 0, 0, 0);
            }
            packv<<<NB * NH * (SEQ / 2) * HIDX / 256, 256>>>(vdh, vdl, vph, vpl);

            // scores = Q @ K^T per (b,h)
            bgemm<<<dim3(16, 8, 32), 256, SMEMSZ>>>(
                qh, ql, 256, 2097152, 262144, kh, kl, 256, 2097152, 262144,
                sc, SEQ, 8388608, 1048576,
                nullptr, nullptr, nullptr, nullptr, nullptr, nullptr, 0, 0, 0,
                nullptr, HIDX, 1, msk, 0);
            softmax_kernel<<<NB * NH * SEQ, 256>>>(sc, ath, atl, msk);

            // O2 = attn @ V -> packed
            bgemm<<<dim3(8, 8, 32), 256, SMEMSZ>>>(
                ath, atl, 512, 4194304, 524288, vph, vpl, 512, 2097152, 262144,
                nullptr, 0, 0, 0,
                o2h, o2l, nullptr, nullptr, nullptr, nullptr, 2048, 2097152, 256,
                nullptr, SEQ, 0, 0, msk);

            // out projection
            size_t wPo = (size_t)(l * 2 + a) * 1048576;
            bgemm<<<dim3(8, 32, 1), 256, SMEMSZ>>>(
                o2h, o2l, 2048, 0, 0, woh + wPo, wol + wPo, HIDX, 0, 0,
                t1, HIDX, 0, 0,
                nullptr, nullptr, nullptr, nullptr, nullptr, nullptr, 0, 0, 0,
                bo + (size_t)(l * 2 + a) * HIDX, HH, 0, 0, 0);

            ln_kernel<<<TOK, 256>>>(t1, xb, lng + (size_t)(l * 3 + a) * HIDX,
                                    lnb + (size_t)(l * 3 + a) * HIDX, xb, xph, xpl);
        }
        gate_kernel<<<TOK / 8, 256>>>(xb, gw + (size_t)l * HIDX * NE, gb + (size_t)l * NE);
        moe_setup<<<1, 256>>>();
        moe_gemm1<<<dim3(FFN / 64, MAXT), 256>>>(xb, w1 + (size_t)l * NE * HIDX * FFN,
                                                 b1 + (size_t)l * NE * FFN);
        moe_gemm2<<<dim3(HIDX / 64, MAXT), 256>>>(w2 + (size_t)l * NE * FFN * HIDX,
                                                  b2 + (size_t)l * NE * HIDX);
        float* lnOut = (l == NL - 1) ? out : xb;
        ln_kernel<<<TOK, 256>>>(yb, xb, lng + (size_t)(l * 3 + 2) * HIDX,
                                lnb + (size_t)(l * 3 + 2) * HIDX, lnOut, xph, xpl);
    }
}

// round 14
// speedup vs baseline: 1.0065x; 1.0008x over previous
#include <cuda_runtime.h>
#include <cuda_bf16.h>
#include <cstdint>

#define NL 2
#define NH 8
#define SEQ 1024
#define HIDX 512
#define HH 4096
#define NE 8
#define FFN 1024
#define NB 4
#define TOK 4096
#define EPSV 1e-5f
#define MAXROWS 4608
#define MAXT 72
#define SMEMSZ 55296
#define NQKV 12288

// fp32 buffers
static __device__ float g_sc[(size_t)NB * NH * SEQ * SEQ];
static __device__ float g_t1[(size_t)TOK * HIDX];
static __device__ float g_x[(size_t)TOK * HIDX];
static __device__ float g_y[(size_t)TOK * HIDX];
static __device__ float g_h[(size_t)MAXROWS * FFN];
static __device__ float g_bcat[NL * 2 * NQKV];
static __device__ int   g_sel[TOK];
static __device__ float g_wsel[TOK];
static __device__ int   g_perm[MAXROWS];
static __device__ int   g_texp[MAXT];

// packed bf16-pair buffers (hi/lo), 16B aligned for cp.async
#define PKA __device__ __align__(16)
static PKA uint32_t g_qh[(size_t)TOK * HH / 2], g_ql[(size_t)TOK * HH / 2];
static PKA uint32_t g_kh[(size_t)TOK * HH / 2], g_kl[(size_t)TOK * HH / 2];
static PKA uint32_t g_vdh[(size_t)TOK * HH / 2], g_vdl[(size_t)TOK * HH / 2];
static PKA uint32_t g_vph[(size_t)NB * NH * (SEQ / 2) * HIDX], g_vpl[(size_t)NB * NH * (SEQ / 2) * HIDX];
static PKA uint32_t g_o2h[(size_t)TOK * HH / 2], g_o2l[(size_t)TOK * HH / 2];
static PKA uint32_t g_ath[(size_t)NB * NH * SEQ * SEQ / 2], g_atl[(size_t)NB * NH * SEQ * SEQ / 2];
static PKA uint32_t g_xph[TOK * HIDX / 2], g_xpl[TOK * HIDX / 2];
static PKA uint32_t g_eph[TOK * HIDX / 2], g_epl[TOK * HIDX / 2];
// fused QKV weights: [slab][256 kp][12288]
static PKA uint32_t g_wah[(size_t)NL * 2 * (HIDX / 2) * NQKV], g_wal[(size_t)NL * 2 * (HIDX / 2) * NQKV];
static PKA uint32_t g_woh[(size_t)NL * 2 * HH / 2 * HIDX], g_wol[(size_t)NL * 2 * HH / 2 * HIDX];

__device__ __forceinline__ void split2(float x, float y, uint32_t& hi, uint32_t& lo)
{
    __nv_bfloat162 h = __floats2bfloat162_rn(x, y);
    float2 hf = __bfloat1622float2(h);
    __nv_bfloat162 l = __floats2bfloat162_rn(x - hf.x, y - hf.y);
    hi = *(uint32_t*)&h;
    lo = *(uint32_t*)&l;
}

#define MMA_BF16(d, a, b)                                                     \
    asm volatile(                                                             \
        "mma.sync.aligned.m16n8k16.row.col.f32.bf16.bf16.f32 "                \
        "{%0,%1,%2,%3},{%4,%5,%6,%7},{%8,%9},{%0,%1,%2,%3};"                  \
        : "+f"(d[0]), "+f"(d[1]), "+f"(d[2]), "+f"(d[3])                      \
        : "r"(a[0]), "r"(a[1]), "r"(a[2]), "r"(a[3]), "r"(b[0]), "r"(b[1]))

// ---------------------------------------------------------------------------
// Packed split-bf16 mma.sync GEMM (round-6 proven inner loop, untouched).
// Epilogue: component select (Cph2/Cph3) for fused QKV output ranges.
// A-source select: blocks with col0 >= 8192 use A2h/A2l (fused cross-attn:
// Q,K from encoder; V columns from x). Decided once at block start.
// ---------------------------------------------------------------------------
__global__ void __launch_bounds__(256) bgemm(
    const uint32_t* __restrict__ Ah, const uint32_t* __restrict__ Al,
    const uint32_t* __restrict__ A2h, const uint32_t* __restrict__ A2l,
    int ldaP, long long aSb, long long aSh,
    const uint32_t* __restrict__ Bh, const uint32_t* __restrict__ Bl,
    int ldbB, long long bSb, long long bSh,
    float* __restrict__ C, int ldc, long long cSb, long long cSh,
    uint32_t* __restrict__ Cph, uint32_t* __restrict__ Cpl,
    uint32_t* __restrict__ Cph2, uint32_t* __restrict__ Cpl2,
    uint32_t* __restrict__ Cph3, uint32_t* __restrict__ Cpl3,
    int ldcP, long long cpSb, long long cpSh,
    const float* __restrict__ bias,
    int K, int transB, int causalSkip, int causalK)
{
    int row0 = blockIdx.y * 128;
    int col0 = blockIdx.x * 64;
    if (causalSkip && col0 >= row0 + 128) return;
    long long zb = blockIdx.z >> 3, zh = blockIdx.z & 7;
    if (A2h && col0 >= 8192) { Ah = A2h; Al = A2l; }
    Ah += zb * aSb + zh * aSh;
    Al += zb * aSb + zh * aSh;
    Bh += zb * bSb + zh * bSh;
    Bl += zb * bSb + zh * bSh;

    extern __shared__ uint32_t sm[];
    uint32_t smBase = (uint32_t)__cvta_generic_to_shared(sm);

    int tid = threadIdx.x;
    int warp = tid >> 5, lane = tid & 31;
    int wm0 = (warp >> 1) << 5;
    int wn0 = (warp & 1) << 5;
    int tg = lane & 3, gp = lane >> 2;

    const uint32_t* pAh = Ah + (long long)(row0 + (tid >> 1)) * ldaP + ((tid & 1) << 2);
    const uint32_t* pAl = Al + (long long)(row0 + (tid >> 1)) * ldaP + ((tid & 1) << 2);
    int aOff = (tid >> 1) * 12 + ((tid & 1) << 2);

    const uint32_t* pB;
    int bOff;
    int bBase = (tid < 128) ? 9216 : 11520;
    int tt = tid & 127;
    long long bStep;
    if (!transB) {
        int kp = tt >> 4, cc = (tt & 15) << 2;
        pB = (tid < 128 ? Bh : Bl) + (long long)kp * ldbB + col0 + cc;
        bOff = kp * 72 + cc;
        bStep = ldbB;
    } else {
        int nn = tt >> 1, cc = (tt & 1) << 2;
        pB = (tid < 128 ? Bh : Bl) + (long long)(col0 + nn) * ldbB + cc;
        bOff = nn * 12 + cc;
        bStep = 1;
    }

#define CPA(doff, src)                                                        \
    asm volatile("cp.async.cg.shared.global [%0], [%1], 16;"                  \
                 :: "r"(smBase + ((doff) << 2)), "l"(src))
#define ISSUE(st, kp0)                                                        \
    do {                                                                      \
        CPA((st) * 1536 + aOff, pAh + (kp0));                                 \
        CPA(4608 + (st) * 1536 + aOff, pAl + (kp0));                          \
        CPA(bBase + (st) * 768 + bOff, pB + (long long)(kp0) * bStep);        \
    } while (0)
#define COMMIT asm volatile("cp.async.commit_group;" ::)

    int kend = causalK ? (row0 + 128) : K;
    int niter = kend >> 4;

    ISSUE(0, 0);
    COMMIT;
    if (niter > 1) ISSUE(1, 8);
    COMMIT;

    float acc[2][4][4];
#pragma unroll
    for (int i = 0; i < 2; i++)
#pragma unroll
        for (int j = 0; j < 4; j++)
#pragma unroll
            for (int t = 0; t < 4; t++) acc[i][j][t] = 0.f;

    for (int i = 0; i < niter; i++) {
        if (i + 1 < niter) asm volatile("cp.async.wait_group 1;" ::);
        else               asm volatile("cp.async.wait_group 0;" ::);
        __syncthreads();
        if (i + 2 < niter) {
            int s2 = (i + 2) % 3;
            ISSUE(s2, (i + 2) * 8);
        }
        COMMIT;

        int s = i % 3;
        const uint32_t* aHs = sm + s * 1536;
        const uint32_t* aLs = sm + 4608 + s * 1536;
        const uint32_t* bHs = sm + 9216 + s * 768;
        const uint32_t* bLs = sm + 11520 + s * 768;

        uint32_t aF[2][4], aG[2][4], bF[4][2], bG[4][2];
#pragma unroll
        for (int mt = 0; mt < 2; mt++) {
            int m = wm0 + mt * 16 + gp;
            aF[mt][0] = aHs[m * 12 + tg];
            aF[mt][1] = aHs[(m + 8) * 12 + tg];
            aF[mt][2] = aHs[m * 12 + tg + 4];
            aF[mt][3] = aHs[(m + 8) * 12 + tg + 4];
            aG[mt][0] = aLs[m * 12 + tg];
            aG[mt][1] = aLs[(m + 8) * 12 + tg];
            aG[mt][2] = aLs[m * 12 + tg + 4];
            aG[mt][3] = aLs[(m + 8) * 12 + tg + 4];
        }
        if (!transB) {
#pragma unroll
            for (int nt = 0; nt < 4; nt++) {
                int n = wn0 + nt * 8 + gp;
                bF[nt][0] = bHs[tg * 72 + n];
                bF[nt][1] = bHs[(tg + 4) * 72 + n];
                bG[nt][0] = bLs[tg * 72 + n];
                bG[nt][1] = bLs[(tg + 4) * 72 + n];
            }
        } else {
#pragma unroll
            for (int nt = 0; nt < 4; nt++) {
                int n = wn0 + nt * 8 + gp;
                bF[nt][0] = bHs[n * 12 + tg];
                bF[nt][1] = bHs[n * 12 + tg + 4];
                bG[nt][0] = bLs[n * 12 + tg];
                bG[nt][1] = bLs[n * 12 + tg + 4];
            }
        }
#pragma unroll
        for (int mt = 0; mt < 2; mt++)
#pragma unroll
            for (int nt = 0; nt < 4; nt++) {
                MMA_BF16(acc[mt][nt], aF[mt], bF[nt]);
                MMA_BF16(acc[mt][nt], aF[mt], bG[nt]);
                MMA_BF16(acc[mt][nt], aG[mt], bF[nt]);
            }
    }

    if (Cph) {
        uint32_t* oph = Cph;
        uint32_t* opl = Cpl;
        int cbase = 0;
        if (Cph3 && col0 >= 8192)      { oph = Cph3; opl = Cpl3; cbase = 8192; }
        else if (Cph2 && col0 >= 4096) { oph = Cph2; opl = Cpl2; cbase = 4096; }
        oph += zb * cpSb + zh * cpSh;
        opl += zb * cpSb + zh * cpSh;
#pragma unroll
        for (int mt = 0; mt < 2; mt++) {
            long long r = row0 + wm0 + mt * 16 + gp;
#pragma unroll
            for (int nt = 0; nt < 4; nt++) {
                int c = col0 + wn0 + nt * 8 + tg * 2;
                float b0 = bias ? bias[c] : 0.f;
                float b1 = bias ? bias[c + 1] : 0.f;
                int cp = (c - cbase) >> 1;
                uint32_t h, l;
                split2(acc[mt][nt][0] + b0, acc[mt][nt][1] + b1, h, l);
                oph[r * ldcP + cp] = h;
                opl[r * ldcP + cp] = l;
                split2(acc[mt][nt][2] + b0, acc[mt][nt][3] + b1, h, l);
                oph[(r + 8) * ldcP + cp] = h;
                opl[(r + 8) * ldcP + cp] = l;
            }
        }
    } else {
        C += zb * cSb + zh * cSh;
#pragma unroll
        for (int mt = 0; mt < 2; mt++) {
            long long r = row0 + wm0 + mt * 16 + gp;
#pragma unroll
            for (int nt = 0; nt < 4; nt++) {
                int c = col0 + wn0 + nt * 8 + tg * 2;
                float b0 = bias ? bias[c] : 0.f;
                float b1 = bias ? bias[c + 1] : 0.f;
                float2 lo = make_float2(acc[mt][nt][0] + b0, acc[mt][nt][1] + b1);
                float2 hi = make_float2(acc[mt][nt][2] + b0, acc[mt][nt][3] + b1);
                *(float2*)(C + r * ldc + c) = lo;
                *(float2*)(C + (r + 8) * ldc + c) = hi;
            }
        }
    }
#undef CPA
#undef ISSUE
#undef COMMIT
}

// ---------------------------------------------------------------------------
// Pre-split kernels
// ---------------------------------------------------------------------------
__global__ void __launch_bounds__(256) packrows(const float* __restrict__ src,
                                                uint32_t* __restrict__ h, uint32_t* __restrict__ l)
{
    int idx = blockIdx.x * 256 + threadIdx.x;
    float2 v = ((const float2*)src)[idx];
    split2(v.x, v.y, h[idx], l[idx]);
}

__global__ void __launch_bounds__(256) packcols(const float* __restrict__ src,
                                                uint32_t* __restrict__ h, uint32_t* __restrict__ l,
                                                int logN)
{
    int idx = blockIdx.x * 256 + threadIdx.x;
    int kp = idx >> logN;
    int c = idx & ((1 << logN) - 1);
    const float* p = src + (((size_t)kp * 2) << logN) + c;
    split2(p[0], p[1 << logN], h[idx], l[idx]);
}

// fused QKV weight pack: out[slab][kp][12288] = pairs along K of wq|wk|wv cols
__global__ void __launch_bounds__(256) packqkv(const float* __restrict__ wq,
                                               const float* __restrict__ wk,
                                               const float* __restrict__ wv,
                                               uint32_t* __restrict__ h,
                                               uint32_t* __restrict__ l)
{
    int idx = blockIdx.x * 256 + threadIdx.x;
    int slab = idx / (256 * NQKV);
    int rem = idx - slab * (256 * NQKV);
    int kp = rem / NQKV;
    int c = rem - kp * NQKV;
    int comp = c >> 12;
    int c2 = c & 4095;
    const float* W = (comp == 0) ? wq : (comp == 1) ? wk : wv;
    W += (size_t)slab * HIDX * HH;
    float a = W[(size_t)(2 * kp) * HH + c2];
    float b = W[(size_t)(2 * kp + 1) * HH + c2];
    split2(a, b, h[idx], l[idx]);
}

__global__ void __launch_bounds__(256) packbias(const float* __restrict__ bq,
                                                const float* __restrict__ bk,
                                                const float* __restrict__ bv,
                                                float* __restrict__ bcat)
{
    int idx = blockIdx.x * 256 + threadIdx.x;
    int slab = idx / NQKV;
    int c = idx - slab * NQKV;
    int comp = c >> 12;
    int c2 = c & 4095;
    const float* src = (comp == 0) ? bq : (comp == 1) ? bk : bv;
    bcat[idx] = src[slab * HH + c2];
}

// reconstruct fp32 V element at flat quirk index f from packed d-pair buffers
__device__ __forceinline__ float vread(const uint32_t* __restrict__ vh,
                                       const uint32_t* __restrict__ vl, size_t f)
{
    size_t p = (f >> 12) * 2048 + ((f & 4095) >> 1);
    __nv_bfloat162 h = *(const __nv_bfloat162*)&vh[p];
    __nv_bfloat162 l = *(const __nv_bfloat162*)&vl[p];
    float2 hf = __bfloat1622float2(h);
    float2 lf = __bfloat1622float2(l);
    return (f & 1) ? (hf.y + lf.y) : (hf.x + lf.x);
}

// V packed d-pairs -> packed [b][h][jp][d] (pairs along seq j)
__global__ void __launch_bounds__(256) packv(const uint32_t* __restrict__ vh,
                                             const uint32_t* __restrict__ vl,
                                             uint32_t* __restrict__ h, uint32_t* __restrict__ l)
{
    int idx = blockIdx.x * 256 + threadIdx.x;
    int b  = idx >> 21;
    int hh = (idx >> 18) & 7;
    int jp = (idx >> 9) & 511;
    int d  = idx & 511;
    size_t f = (size_t)b * 4194304 + (size_t)hh * 524288 + (size_t)jp * 1024 + d;
    split2(vread(vh, vl, f), vread(vh, vl, f + 512), h[idx], l[idx]);
}

// ---------------------------------------------------------------------------
// Softmax over rows of SEQ; writes packed bf16 hi/lo probabilities.
// ---------------------------------------------------------------------------
__global__ void __launch_bounds__(256) softmax_kernel(const float* __restrict__ sc,
                                                      uint32_t* __restrict__ ath,
                                                      uint32_t* __restrict__ atl, int masked)
{
    long long base = (long long)blockIdx.x * SEQ;
    long long pbase = (long long)blockIdx.x * (SEQ / 2);
    int i = blockIdx.x & (SEQ - 1);
    int n = masked ? (i + 1) : SEQ;
    int tid = threadIdx.x;
    __shared__ float red[8];

    float v[2][2];
    float mx = -1e30f;
#pragma unroll
    for (int j = 0; j < 2; j++) {
        int c = (tid + (j << 8)) << 1;
        float2 t = *(const float2*)(sc + base + c);
        v[j][0] = (c < n) ? t.x : -1e30f;
        v[j][1] = (c + 1 < n) ? t.y : -1e30f;
        mx = fmaxf(mx, fmaxf(v[j][0], v[j][1]));
    }
#pragma unroll
    for (int o = 16; o; o >>= 1) mx = fmaxf(mx, __shfl_xor_sync(0xffffffffu, mx, o));
    if ((tid & 31) == 0) red[tid >> 5] = mx;
    __syncthreads();
    mx = red[0];
#pragma unroll
    for (int w = 1; w < 8; w++) mx = fmaxf(mx, red[w]);
    __syncthreads();

    float s = 0.f;
#pragma unroll
    for (int j = 0; j < 2; j++) {
        int c = (tid + (j << 8)) << 1;
        v[j][0] = (c < n) ? __expf(v[j][0] - mx) : 0.f;
        v[j][1] = (c + 1 < n) ? __expf(v[j][1] - mx) : 0.f;
        s += v[j][0] + v[j][1];
    }
#pragma unroll
    for (int o = 16; o; o >>= 1) s += __shfl_xor_sync(0xffffffffu, s, o);
    if ((tid & 31) == 0) red[tid >> 5] = s;
    __syncthreads();
    s = 0.f;
#pragma unroll
    for (int w = 0; w < 8; w++) s += red[w];
    float inv = 1.f / s;
#pragma unroll
    for (int j = 0; j < 2; j++) {
        uint32_t h, l;
        split2(v[j][0] * inv, v[j][1] * inv, h, l);
        ath[pbase + tid + (j << 8)] = h;
        atl[pbase + tid + (j << 8)] = l;
    }
}

// ---------------------------------------------------------------------------
// y = LayerNorm(a + r); also writes packed bf16 hi/lo of y.
// ---------------------------------------------------------------------------
__global__ void __launch_bounds__(256) ln_kernel(
    const float* __restrict__ a, const float* __restrict__ r,
    const float* __restrict__ g, const float* __restrict__ b,
    float* __restrict__ y, uint32_t* __restrict__ yph, uint32_t* __restrict__ ypl)
{
    long long base = (long long)blockIdx.x * HIDX;
    int tid = threadIdx.x;
    int c = tid << 1;
    __shared__ float red[8];

    float2 av = *(const float2*)(a + base + c);
    float2 rv = *(const float2*)(r + base + c);
    float z0 = av.x + rv.x, z1 = av.y + rv.y;
    float s = z0 + z1;
#pragma unroll
    for (int o = 16; o; o >>= 1) s += __shfl_xor_sync(0xffffffffu, s, o);
    if ((tid & 31) == 0) red[tid >> 5] = s;
    __syncthreads();
    s = 0.f;
#pragma unroll
    for (int w = 0; w < 8; w++) s += red[w];
    float m = s * (1.f / HIDX);
    float d0 = z0 - m, d1 = z1 - m;
    float qs = d0 * d0 + d1 * d1;
    __syncthreads();
#pragma unroll
    for (int o = 16; o; o >>= 1) qs += __shfl_xor_sync(0xffffffffu, qs, o);
    if ((tid & 31) == 0) red[tid >> 5] = qs;
    __syncthreads();
    qs = 0.f;
#pragma unroll
    for (int w = 0; w < 8; w++) qs += red[w];
    float inv = rsqrtf(qs * (1.f / HIDX) + EPSV);
    float2 gg = *(const float2*)(g + c);
    float2 bb = *(const float2*)(b + c);
    float o0 = gg.x * d0 * inv + bb.x;
    float o1 = gg.y * d1 * inv + bb.y;
    *(float2*)(y + base + c) = make_float2(o0, o1);
    uint32_t h, l;
    split2(o0, o1, h, l);
    yph[(long long)blockIdx.x * 256 + tid] = h;
    ypl[(long long)blockIdx.x * 256 + tid] = l;
}

// ---------------------------------------------------------------------------
// Gate: softmax over E=8, pick 2nd-largest (faithful TOPK-1 bug).
// ---------------------------------------------------------------------------
__global__ void __launch_bounds__(256) gate_kernel(
    const float* __restrict__ x, const float* __restrict__ gw, const float* __restrict__ gb)
{
    int tok = (blockIdx.x << 3) + (threadIdx.x >> 5);
    int lane = threadIdx.x & 31;
    const float* xr = x + (size_t)tok * HIDX;
    float acc[8] = {0, 0, 0, 0, 0, 0, 0, 0};
    for (int j = lane; j < HIDX; j += 32) {
        float xv = xr[j];
        float4 a0 = *(const float4*)(gw + j * 8);
        float4 a1 = *(const float4*)(gw + j * 8 + 4);
        acc[0] += xv * a0.x; acc[1] += xv * a0.y; acc[2] += xv * a0.z; acc[3] += xv * a0.w;
        acc[4] += xv * a1.x; acc[5] += xv * a1.y; acc[6] += xv * a1.z; acc[7] += xv * a1.w;
    }
#pragma unroll
    for (int e = 0; e < 8; e++)
#pragma unroll
        for (int o = 16; o; o >>= 1) acc[e] += __shfl_xor_sync(0xffffffffu, acc[e], o);
    if (lane == 0) {
        float mx = -1e30f;
#pragma unroll
        for (int e = 0; e < 8; e++) { acc[e] += gb[e]; mx = fmaxf(mx, acc[e]); }
        float p[8];
#pragma unroll
        for (int e = 0; e < 8; e++) p[e] = __expf(acc[e] - mx);
        float v1 = -1.f, v2 = -1.f; int i1 = 0, i2 = 0;
#pragma unroll
        for (int e = 0; e < 8; e++) {
            if (p[e] > v1)      { v2 = v1; i2 = i1; v1 = p[e]; i1 = e; }
            else if (p[e] > v2) { v2 = p[e]; i2 = e; }
        }
        g_sel[tok] = i2;
        g_wsel[tok] = v2 / (v1 + v2);
    }
}

__global__ void __launch_bounds__(256) moe_setup()
{
    __shared__ int cnt[8], cursor[8];
    int tid = threadIdx.x;
    if (tid < 8) cnt[tid] = 0;
    for (int i = tid; i < MAXROWS; i += 256) g_perm[i] = -1;
    __syncthreads();
    for (int i = tid; i < TOK; i += 256) atomicAdd(&cnt[g_sel[i]], 1);
    __syncthreads();
    if (tid == 0) {
        int base = 0, t = 0;
        for (int e = 0; e < 8; e++) {
            cursor[e] = base;
            int tiles = (cnt[e] + 63) >> 6;
            for (int j = 0; j < tiles; j++) g_texp[t++] = e;
            base += tiles << 6;
        }
        for (; t < MAXT; t++) g_texp[t] = -1;
    }
    __syncthreads();
    for (int i = tid; i < TOK; i += 256) {
        int e = g_sel[i];
        int p = atomicAdd(&cursor[e], 1);
        g_perm[p] = i;
    }
}

__global__ void __launch_bounds__(256) moe_gemm1(
    const float* __restrict__ x, const float* __restrict__ w1, const float* __restrict__ b1)
{
    int t = blockIdx.y;
    int e = g_texp[t];
    if (e < 0) return;
    const float* B = w1 + (size_t)e * HIDX * FFN;
    const float* bias = b1 + (size_t)e * FFN;
    int col0 = blockIdx.x << 6;
    __shared__ float As[16][68];
    __shared__ float Bs[16][68];
    __shared__ int rows[64];
    int tid = threadIdx.x;
    if (tid < 64) rows[tid] = g_perm[(t << 6) + tid];
    __syncthreads();
    int tx = tid & 15, ty = tid >> 4;
    float acc[4][4] = {};
    for (int k0 = 0; k0 < HIDX; k0 += 16) {
        int mm = tid >> 2, k4 = (tid & 3) << 2;
        int r = rows[mm];
        float4 va = make_float4(0.f, 0.f, 0.f, 0.f);
        if (r >= 0) va = *(const float4*)(x + (size_t)r * HIDX + k0 + k4);
        As[k4 + 0][mm] = va.x; As[k4 + 1][mm] = va.y;
        As[k4 + 2][mm] = va.z; As[k4 + 3][mm] = va.w;
        int kk = tid >> 4, nn = (tid & 15) << 2;
        float4 vb = *(const float4*)(B + (size_t)(k0 + kk) * FFN + col0 + nn);
        Bs[kk][nn] = vb.x; Bs[kk][nn + 1] = vb.y;
        Bs[kk][nn + 2] = vb.z; Bs[kk][nn + 3] = vb.w;
        __syncthreads();
#pragma unroll
        for (int kk2 = 0; kk2 < 16; kk2++) {
            float av[4], bv[4];
#pragma unroll
            for (int i = 0; i < 4; i++) av[i] = As[kk2][ty * 4 + i];
#pragma unroll
            for (int j = 0; j < 4; j++) bv[j] = Bs[kk2][tx * 4 + j];
#pragma unroll
            for (int i = 0; i < 4; i++)
#pragma unroll
                for (int j = 0; j < 4; j++)
                    acc[i][j] = fmaf(av[i], bv[j], acc[i][j]);
        }
        __syncthreads();
    }
#pragma unroll
    for (int i = 0; i < 4; i++) {
#pragma unroll
        for (int j = 0; j < 4; j++) {
            int c = col0 + tx * 4 + j;
            float vv = acc[i][j] + bias[c];
            vv = fmaxf(vv, 0.f);
            g_h[(size_t)((t << 6) + ty * 4 + i) * FFN + c] = vv;
        }
    }
}

__global__ void __launch_bounds__(256) moe_gemm2(
    const float* __restrict__ w2, const float* __restrict__ b2)
{
    int t = blockIdx.y;
    int e = g_texp[t];
    if (e < 0) return;
    const float* B = w2 + (size_t)e * FFN * HIDX;
    const float* bias = b2 + (size_t)e * HIDX;
    int col0 = blockIdx.x << 6;
    __shared__ float As[16][68];
    __shared__ float Bs[16][68];
    __shared__ int rows[64];
    int tid = threadIdx.x;
    if (tid < 64) rows[tid] = g_perm[(t << 6) + tid];
    __syncthreads();
    int tx = tid & 15, ty = tid >> 4;
    float acc[4][4] = {};
    for (int k0 = 0; k0 < FFN; k0 += 16) {
        int mm = tid >> 2, k4 = (tid & 3) << 2;
        float4 va = *(const float4*)(&g_h[(size_t)((t << 6) + mm) * FFN + k0 + k4]);
        As[k4 + 0][mm] = va.x; As[k4 + 1][mm] = va.y;
        As[k4 + 2][mm] = va.z; As[k4 + 3][mm] = va.w;
        int kk = tid >> 4, nn = (tid & 15) << 2;
        float4 vb = *(const float4*)(B + (size_t)(k0 + kk) * HIDX + col0 + nn);
        Bs[kk][nn] = vb.x; Bs[kk][nn + 1] = vb.y;
        Bs[kk][nn + 2] = vb.z; Bs[kk][nn + 3] = vb.w;
        __syncthreads();
#pragma unroll
        for (int kk2 = 0; kk2 < 16; kk2++) {
            float av[4], bv[4];
#pragma unroll
            for (int i = 0; i < 4; i++) av[i] = As[kk2][ty * 4 + i];
#pragma unroll
            for (int j = 0; j < 4; j++) bv[j] = Bs[kk2][tx * 4 + j];
#pragma unroll
            for (int i = 0; i < 4; i++)
#pragma unroll
                for (int j = 0; j < 4; j++)
                    acc[i][j] = fmaf(av[i], bv[j], acc[i][j]);
        }
        __syncthreads();
    }
#pragma unroll
    for (int i = 0; i < 4; i++) {
        int r = rows[ty * 4 + i];
        if (r < 0) continue;
        float ws = g_wsel[r];
#pragma unroll
        for (int j = 0; j < 4; j++) {
            int c = col0 + tx * 4 + j;
            g_y[(size_t)r * HIDX + c] = (acc[i][j] + bias[c]) * ws;
        }
    }
}

__global__ void __launch_bounds__(256) copy_kernel(float* __restrict__ dst,
                                                   const float* __restrict__ src, int n)
{
    int i = blockIdx.x * 256 + threadIdx.x;
    if (i < n) dst[i] = src[i];
}

// ---------------------------------------------------------------------------
extern "C" void kernel_launch(void* const* d_in, const int* in_sizes, int n_in,
                              void* d_out, int out_size)
{
    const float* x_in = (const float*)d_in[0];
    const float* enc  = (const float*)d_in[1];
    const float* wq = (const float*)d_in[2];
    const float* bq = (const float*)d_in[3];
    const float* wk = (const float*)d_in[4];
    const float* bk = (const float*)d_in[5];
    const float* wv = (const float*)d_in[6];
    const float* bv = (const float*)d_in[7];
    const float* wo = (const float*)d_in[8];
    const float* bo = (const float*)d_in[9];
    const float* gw = (const float*)d_in[10];
    const float* gb = (const float*)d_in[11];
    const float* w1 = (const float*)d_in[12];
    const float* b1 = (const float*)d_in[13];
    const float* w2 = (const float*)d_in[14];
    const float* b2 = (const float*)d_in[15];
    const float* lng = (const float*)d_in[16];
    const float* lnb = (const float*)d_in[17];
    float* out = (float*)d_out;

    cudaFuncSetAttribute(bgemm, cudaFuncAttributeMaxDynamicSharedMemorySize, SMEMSZ);

    float *sc, *t1, *xb, *yb, *bcat;
    uint32_t *qh, *ql, *kh, *kl, *vdh, *vdl, *vph, *vpl, *o2h, *o2l, *ath, *atl;
    uint32_t *xph, *xpl, *eph, *epl;
    uint32_t *wah, *wal, *woh, *wol;
    cudaGetSymbolAddress((void**)&sc,  g_sc);
    cudaGetSymbolAddress((void**)&t1,  g_t1);
    cudaGetSymbolAddress((void**)&xb,  g_x);
    cudaGetSymbolAddress((void**)&yb,  g_y);
    cudaGetSymbolAddress((void**)&bcat, g_bcat);
    cudaGetSymbolAddress((void**)&qh,  g_qh);  cudaGetSymbolAddress((void**)&ql, g_ql);
    cudaGetSymbolAddress((void**)&kh,  g_kh);  cudaGetSymbolAddress((void**)&kl, g_kl);
    cudaGetSymbolAddress((void**)&vdh, g_vdh); cudaGetSymbolAddress((void**)&vdl, g_vdl);
    cudaGetSymbolAddress((void**)&vph, g_vph); cudaGetSymbolAddress((void**)&vpl, g_vpl);
    cudaGetSymbolAddress((void**)&o2h, g_o2h); cudaGetSymbolAddress((void**)&o2l, g_o2l);
    cudaGetSymbolAddress((void**)&ath, g_ath); cudaGetSymbolAddress((void**)&atl, g_atl);
    cudaGetSymbolAddress((void**)&xph, g_xph); cudaGetSymbolAddress((void**)&xpl, g_xpl);
    cudaGetSymbolAddress((void**)&eph, g_eph); cudaGetSymbolAddress((void**)&epl, g_epl);
    cudaGetSymbolAddress((void**)&wah, g_wah); cudaGetSymbolAddress((void**)&wal, g_wal);
    cudaGetSymbolAddress((void**)&woh, g_woh); cudaGetSymbolAddress((void**)&wol, g_wol);

    // one-time packing
    packqkv<<<NL * 2 * 256 * NQKV / 256, 256>>>(wq, wk, wv, wah, wal);
    packbias<<<NL * 2 * NQKV / 256, 256>>>(bq, bk, bv, bcat);
    packcols<<<NL * 2 * (HH / 2) * HIDX / 256, 256>>>(wo, woh, wol, 9);
    packrows<<<TOK * HIDX / 2 / 256, 256>>>(enc, eph, epl);
    packrows<<<TOK * HIDX / 2 / 256, 256>>>(x_in, xph, xpl);
    copy_kernel<<<TOK * HIDX / 256, 256>>>(xb, x_in, TOK * HIDX);

    for (int l = 0; l < NL; l++) {
        for (int a = 0; a < 2; a++) {
            const uint32_t* aAh = a ? eph : xph;   // Q/K input (cross: encoder)
            const uint32_t* aAl = a ? epl : xpl;
            size_t wP = (size_t)(l * 2 + a) * 256 * NQKV;
            int msk = (a == 0);

            // fused QKV projection in ONE launch. Q,K read aAh; V columns
            // (col0 >= 8192) read xph via the A-source select. For self-attn
            // (aAh == xph) the select is a no-op.
            bgemm<<<dim3(NQKV / 64, 32, 1), 256, SMEMSZ>>>(
                aAh, aAl, xph, xpl, 256, 0, 0,
                wah + wP, wal + wP, NQKV, 0, 0,
                nullptr, 0, 0, 0,
                qh, ql, kh, kl, vdh, vdl, 2048, 0, 0,
                bcat + (size_t)(l * 2 + a) * NQKV, HIDX, 0, 0, 0);
            packv<<<NB * NH * (SEQ / 2) * HIDX / 256, 256>>>(vdh, vdl, vph, vpl);

            // scores = Q @ K^T per (b,h)
            bgemm<<<dim3(16, 8, 32), 256, SMEMSZ>>>(
                qh, ql, nullptr, nullptr, 256, 2097152, 262144,
                kh, kl, 256, 2097152, 262144,
                sc, SEQ, 8388608, 1048576,
                nullptr, nullptr, nullptr, nullptr, nullptr, nullptr, 0, 0, 0,
                nullptr, HIDX, 1, msk, 0);
            softmax_kernel<<<NB * NH * SEQ, 256>>>(sc, ath, atl, msk);

            // O2 = attn @ V -> packed
            bgemm<<<dim3(8, 8, 32), 256, SMEMSZ>>>(
                ath, atl, nullptr, nullptr, 512, 4194304, 524288,
                vph, vpl, 512, 2097152, 262144,
                nullptr, 0, 0, 0,
                o2h, o2l, nullptr, nullptr, nullptr, nullptr, 2048, 2097152, 256,
                nullptr, SEQ, 0, 0, msk);

            // out projection
            size_t wPo = (size_t)(l * 2 + a) * 1048576;
            bgemm<<<dim3(8, 32, 1), 256, SMEMSZ>>>(
                o2h, o2l, nullptr, nullptr, 2048, 0, 0,
                woh + wPo, wol + wPo, HIDX, 0, 0,
                t1, HIDX, 0, 0,
                nullptr, nullptr, nullptr, nullptr, nullptr, nullptr, 0, 0, 0,
                bo + (size_t)(l * 2 + a) * HIDX, HH, 0, 0, 0);

            ln_kernel<<<TOK, 256>>>(t1, xb, lng + (size_t)(l * 3 + a) * HIDX,
                                    lnb + (size_t)(l * 3 + a) * HIDX, xb, xph, xpl);
        }
        gate_kernel<<<TOK / 8, 256>>>(xb, gw + (size_t)l * HIDX * NE, gb + (size_t)l * NE);
        moe_setup<<<1, 256>>>();
        moe_gemm1<<<dim3(FFN / 64, MAXT), 256>>>(xb, w1 + (size_t)l * NE * HIDX * FFN,
                                                 b1 + (size_t)l * NE * FFN);
        moe_gemm2<<<dim3(HIDX / 64, MAXT), 256>>>(w2 + (size_t)l * NE * FFN * HIDX,
                                                  b2 + (size_t)l * NE * HIDX);
        float* lnOut = (l == NL - 1) ? out : xb;
        ln_kernel<<<TOK, 256>>>(yb, xb, lng + (size_t)(l * 3 + 2) * HIDX,
                                lnb + (size_t)(l * 3 + 2) * HIDX, lnOut, xph, xpl);
    }
}

// round 15
// speedup vs baseline: 1.0488x; 1.0420x over previous
#include <cuda_runtime.h>
#include <cuda_bf16.h>
#include <cstdint>

#define NL 2
#define NH 8
#define SEQ 1024
#define HIDX 512
#define HH 4096
#define NE 8
#define FFN 1024
#define NB 4
#define TOK 4096
#define EPSV 1e-5f
#define MAXROWS2 5120
#define MAXT2 40
#define SMEMSZ 55296
#define NQKV 12288

// fp32 buffers
static __device__ float g_sc[(size_t)NB * NH * SEQ * SEQ];
static __device__ float g_t1[(size_t)TOK * HIDX];
static __device__ float g_x[(size_t)TOK * HIDX];
static __device__ float g_y[(size_t)TOK * HIDX];
static __device__ float g_bcat[NL * 2 * NQKV];
static __device__ int   g_sel[TOK];
static __device__ float g_wsel[TOK];
static __device__ int   g_perm[MAXROWS2];
static __device__ int   g_texp[MAXT2];

// packed bf16-pair buffers (hi/lo), 16B aligned for cp.async
#define PKA __device__ __align__(16)
static PKA uint32_t g_qh[(size_t)TOK * HH / 2], g_ql[(size_t)TOK * HH / 2];
static PKA uint32_t g_kh[(size_t)TOK * HH / 2], g_kl[(size_t)TOK * HH / 2];
static PKA uint32_t g_vdh[(size_t)TOK * HH / 2], g_vdl[(size_t)TOK * HH / 2];
static PKA uint32_t g_vph[(size_t)NB * NH * (SEQ / 2) * HIDX], g_vpl[(size_t)NB * NH * (SEQ / 2) * HIDX];
static PKA uint32_t g_o2h[(size_t)TOK * HH / 2], g_o2l[(size_t)TOK * HH / 2];
static PKA uint32_t g_ath[(size_t)NB * NH * SEQ * SEQ / 2], g_atl[(size_t)NB * NH * SEQ * SEQ / 2];
static PKA uint32_t g_xph[TOK * HIDX / 2], g_xpl[TOK * HIDX / 2];
static PKA uint32_t g_eph[TOK * HIDX / 2], g_epl[TOK * HIDX / 2];
static PKA uint32_t g_xgh[(size_t)MAXROWS2 * 256], g_xgl[(size_t)MAXROWS2 * 256];
static PKA uint32_t g_hph[(size_t)MAXROWS2 * 512], g_hpl[(size_t)MAXROWS2 * 512];
// fused QKV weights: [slab][256 kp][12288]
static PKA uint32_t g_wah[(size_t)NL * 2 * (HIDX / 2) * NQKV], g_wal[(size_t)NL * 2 * (HIDX / 2) * NQKV];
static PKA uint32_t g_woh[(size_t)NL * 2 * HH / 2 * HIDX], g_wol[(size_t)NL * 2 * HH / 2 * HIDX];
static PKA uint32_t g_w1h[(size_t)NL * NE * 256 * FFN], g_w1l[(size_t)NL * NE * 256 * FFN];
static PKA uint32_t g_w2h[(size_t)NL * NE * 512 * HIDX], g_w2l[(size_t)NL * NE * 512 * HIDX];

__device__ __forceinline__ void split2(float x, float y, uint32_t& hi, uint32_t& lo)
{
    __nv_bfloat162 h = __floats2bfloat162_rn(x, y);
    float2 hf = __bfloat1622float2(h);
    __nv_bfloat162 l = __floats2bfloat162_rn(x - hf.x, y - hf.y);
    hi = *(uint32_t*)&h;
    lo = *(uint32_t*)&l;
}

#define MMA_BF16(d, a, b)                                                     \
    asm volatile(                                                             \
        "mma.sync.aligned.m16n8k16.row.col.f32.bf16.bf16.f32 "                \
        "{%0,%1,%2,%3},{%4,%5,%6,%7},{%8,%9},{%0,%1,%2,%3};"                  \
        : "+f"(d[0]), "+f"(d[1]), "+f"(d[2]), "+f"(d[3])                      \
        : "r"(a[0]), "r"(a[1]), "r"(a[2]), "r"(a[3]), "r"(b[0]), "r"(b[1]))

// ---------------------------------------------------------------------------
// Packed split-bf16 mma.sync GEMM (round-6 proven inner loop, untouched).
// Prologue extensions: A-source select (fused QKV), expert indirection tExp
// (MoE: per-M-tile expert selects B slab + bias; e<0 -> early return).
// Epilogue extensions: component select (Cph2/3), optional ReLU (packed),
// optional scatter store (acc+bias)*wsel[perm[r]] (MoE gemm2).
// ---------------------------------------------------------------------------
__global__ void __launch_bounds__(256) bgemm(
    const uint32_t* __restrict__ Ah, const uint32_t* __restrict__ Al,
    const uint32_t* __restrict__ A2h, const uint32_t* __restrict__ A2l,
    int ldaP, long long aSb, long long aSh,
    const uint32_t* __restrict__ Bh, const uint32_t* __restrict__ Bl,
    int ldbB, long long bSb, long long bSh,
    float* __restrict__ C, int ldc, long long cSb, long long cSh,
    uint32_t* __restrict__ Cph, uint32_t* __restrict__ Cpl,
    uint32_t* __restrict__ Cph2, uint32_t* __restrict__ Cpl2,
    uint32_t* __restrict__ Cph3, uint32_t* __restrict__ Cpl3,
    int ldcP, long long cpSb, long long cpSh,
    const float* __restrict__ bias,
    int K, int transB, int causalSkip, int causalK,
    const int* __restrict__ tExp, const int* __restrict__ scatPerm,
    const float* __restrict__ wsel, int doRelu, int biasStride)
{
    int row0 = blockIdx.y * 128;
    int col0 = blockIdx.x * 64;
    if (causalSkip && col0 >= row0 + 128) return;
    if (tExp) {
        int e = tExp[blockIdx.y];
        if (e < 0) return;
        Bh += (long long)e * bSb;
        Bl += (long long)e * bSb;
        if (bias) bias += (long long)e * biasStride;
    }
    long long zb = blockIdx.z >> 3, zh = blockIdx.z & 7;
    if (A2h && col0 >= 8192) { Ah = A2h; Al = A2l; }
    Ah += zb * aSb + zh * aSh;
    Al += zb * aSb + zh * aSh;
    if (!tExp) {
        Bh += zb * bSb + zh * bSh;
        Bl += zb * bSb + zh * bSh;
    }

    extern __shared__ uint32_t sm[];
    uint32_t smBase = (uint32_t)__cvta_generic_to_shared(sm);

    int tid = threadIdx.x;
    int warp = tid >> 5, lane = tid & 31;
    int wm0 = (warp >> 1) << 5;
    int wn0 = (warp & 1) << 5;
    int tg = lane & 3, gp = lane >> 2;

    const uint32_t* pAh = Ah + (long long)(row0 + (tid >> 1)) * ldaP + ((tid & 1) << 2);
    const uint32_t* pAl = Al + (long long)(row0 + (tid >> 1)) * ldaP + ((tid & 1) << 2);
    int aOff = (tid >> 1) * 12 + ((tid & 1) << 2);

    const uint32_t* pB;
    int bOff;
    int bBase = (tid < 128) ? 9216 : 11520;
    int tt = tid & 127;
    long long bStep;
    if (!transB) {
        int kp = tt >> 4, cc = (tt & 15) << 2;
        pB = (tid < 128 ? Bh : Bl) + (long long)kp * ldbB + col0 + cc;
        bOff = kp * 72 + cc;
        bStep = ldbB;
    } else {
        int nn = tt >> 1, cc = (tt & 1) << 2;
        pB = (tid < 128 ? Bh : Bl) + (long long)(col0 + nn) * ldbB + cc;
        bOff = nn * 12 + cc;
        bStep = 1;
    }

#define CPA(doff, src)                                                        \
    asm volatile("cp.async.cg.shared.global [%0], [%1], 16;"                  \
                 :: "r"(smBase + ((doff) << 2)), "l"(src))
#define ISSUE(st, kp0)                                                        \
    do {                                                                      \
        CPA((st) * 1536 + aOff, pAh + (kp0));                                 \
        CPA(4608 + (st) * 1536 + aOff, pAl + (kp0));                          \
        CPA(bBase + (st) * 768 + bOff, pB + (long long)(kp0) * bStep);        \
    } while (0)
#define COMMIT asm volatile("cp.async.commit_group;" ::)

    int kend = causalK ? (row0 + 128) : K;
    int niter = kend >> 4;

    ISSUE(0, 0);
    COMMIT;
    if (niter > 1) ISSUE(1, 8);
    COMMIT;

    float acc[2][4][4];
#pragma unroll
    for (int i = 0; i < 2; i++)
#pragma unroll
        for (int j = 0; j < 4; j++)
#pragma unroll
            for (int t = 0; t < 4; t++) acc[i][j][t] = 0.f;

    for (int i = 0; i < niter; i++) {
        if (i + 1 < niter) asm volatile("cp.async.wait_group 1;" ::);
        else               asm volatile("cp.async.wait_group 0;" ::);
        __syncthreads();
        if (i + 2 < niter) {
            int s2 = (i + 2) % 3;
            ISSUE(s2, (i + 2) * 8);
        }
        COMMIT;

        int s = i % 3;
        const uint32_t* aHs = sm + s * 1536;
        const uint32_t* aLs = sm + 4608 + s * 1536;
        const uint32_t* bHs = sm + 9216 + s * 768;
        const uint32_t* bLs = sm + 11520 + s * 768;

        uint32_t aF[2][4], aG[2][4], bF[4][2], bG[4][2];
#pragma unroll
        for (int mt = 0; mt < 2; mt++) {
            int m = wm0 + mt * 16 + gp;
            aF[mt][0] = aHs[m * 12 + tg];
            aF[mt][1] = aHs[(m + 8) * 12 + tg];
            aF[mt][2] = aHs[m * 12 + tg + 4];
            aF[mt][3] = aHs[(m + 8) * 12 + tg + 4];
            aG[mt][0] = aLs[m * 12 + tg];
            aG[mt][1] = aLs[(m + 8) * 12 + tg];
            aG[mt][2] = aLs[m * 12 + tg + 4];
            aG[mt][3] = aLs[(m + 8) * 12 + tg + 4];
        }
        if (!transB) {
#pragma unroll
            for (int nt = 0; nt < 4; nt++) {
                int n = wn0 + nt * 8 + gp;
                bF[nt][0] = bHs[tg * 72 + n];
                bF[nt][1] = bHs[(tg + 4) * 72 + n];
                bG[nt][0] = bLs[tg * 72 + n];
                bG[nt][1] = bLs[(tg + 4) * 72 + n];
            }
        } else {
#pragma unroll
            for (int nt = 0; nt < 4; nt++) {
                int n = wn0 + nt * 8 + gp;
                bF[nt][0] = bHs[n * 12 + tg];
                bF[nt][1] = bHs[n * 12 + tg + 4];
                bG[nt][0] = bLs[n * 12 + tg];
                bG[nt][1] = bLs[n * 12 + tg + 4];
            }
        }
#pragma unroll
        for (int mt = 0; mt < 2; mt++)
#pragma unroll
            for (int nt = 0; nt < 4; nt++) {
                MMA_BF16(acc[mt][nt], aF[mt], bF[nt]);
                MMA_BF16(acc[mt][nt], aF[mt], bG[nt]);
                MMA_BF16(acc[mt][nt], aG[mt], bF[nt]);
            }
    }

    if (scatPerm) {
        // MoE gemm2: scatter fp32 (acc+bias)*wsel[token] to C rows by perm.
#pragma unroll
        for (int mt = 0; mt < 2; mt++) {
            int rl = row0 + wm0 + mt * 16 + gp;
            int rg0 = scatPerm[rl];
            int rg1 = scatPerm[rl + 8];
#pragma unroll
            for (int nt = 0; nt < 4; nt++) {
                int c = col0 + wn0 + nt * 8 + tg * 2;
                float b0 = bias[c], b1v = bias[c + 1];
                if (rg0 >= 0) {
                    float ws = wsel[rg0];
                    *(float2*)(C + (size_t)rg0 * ldc + c) =
                        make_float2((acc[mt][nt][0] + b0) * ws, (acc[mt][nt][1] + b1v) * ws);
                }
                if (rg1 >= 0) {
                    float ws = wsel[rg1];
                    *(float2*)(C + (size_t)rg1 * ldc + c) =
                        make_float2((acc[mt][nt][2] + b0) * ws, (acc[mt][nt][3] + b1v) * ws);
                }
            }
        }
    } else if (Cph) {
        uint32_t* oph = Cph;
        uint32_t* opl = Cpl;
        int cbase = 0;
        if (Cph3 && col0 >= 8192)      { oph = Cph3; opl = Cpl3; cbase = 8192; }
        else if (Cph2 && col0 >= 4096) { oph = Cph2; opl = Cpl2; cbase = 4096; }
        oph += zb * cpSb + zh * cpSh;
        opl += zb * cpSb + zh * cpSh;
#pragma unroll
        for (int mt = 0; mt < 2; mt++) {
            long long r = row0 + wm0 + mt * 16 + gp;
#pragma unroll
            for (int nt = 0; nt < 4; nt++) {
                int c = col0 + wn0 + nt * 8 + tg * 2;
                float b0 = bias ? bias[c] : 0.f;
                float b1 = bias ? bias[c + 1] : 0.f;
                int cp = (c - cbase) >> 1;
                float v0 = acc[mt][nt][0] + b0, v1 = acc[mt][nt][1] + b1;
                float v2 = acc[mt][nt][2] + b0, v3 = acc[mt][nt][3] + b1;
                if (doRelu) {
                    v0 = fmaxf(v0, 0.f); v1 = fmaxf(v1, 0.f);
                    v2 = fmaxf(v2, 0.f); v3 = fmaxf(v3, 0.f);
                }
                uint32_t h, l;
                split2(v0, v1, h, l);
                oph[r * ldcP + cp] = h;
                opl[r * ldcP + cp] = l;
                split2(v2, v3, h, l);
                oph[(r + 8) * ldcP + cp] = h;
                opl[(r + 8) * ldcP + cp] = l;
            }
        }
    } else {
        C += zb * cSb + zh * cSh;
#pragma unroll
        for (int mt = 0; mt < 2; mt++) {
            long long r = row0 + wm0 + mt * 16 + gp;
#pragma unroll
            for (int nt = 0; nt < 4; nt++) {
                int c = col0 + wn0 + nt * 8 + tg * 2;
                float b0 = bias ? bias[c] : 0.f;
                float b1 = bias ? bias[c + 1] : 0.f;
                float2 lo = make_float2(acc[mt][nt][0] + b0, acc[mt][nt][1] + b1);
                float2 hi = make_float2(acc[mt][nt][2] + b0, acc[mt][nt][3] + b1);
                *(float2*)(C + r * ldc + c) = lo;
                *(float2*)(C + (r + 8) * ldc + c) = hi;
            }
        }
    }
#undef CPA
#undef ISSUE
#undef COMMIT
}

#define NOEXTRA nullptr, nullptr, nullptr, 0, 0

// ---------------------------------------------------------------------------
// Pre-split kernels
// ---------------------------------------------------------------------------
__global__ void __launch_bounds__(256) packrows(const float* __restrict__ src,
                                                uint32_t* __restrict__ h, uint32_t* __restrict__ l)
{
    int idx = blockIdx.x * 256 + threadIdx.x;
    float2 v = ((const float2*)src)[idx];
    split2(v.x, v.y, h[idx], l[idx]);
}

__global__ void __launch_bounds__(256) packcols(const float* __restrict__ src,
                                                uint32_t* __restrict__ h, uint32_t* __restrict__ l,
                                                int logN)
{
    int idx = blockIdx.x * 256 + threadIdx.x;
    int kp = idx >> logN;
    int c = idx & ((1 << logN) - 1);
    const float* p = src + (((size_t)kp * 2) << logN) + c;
    split2(p[0], p[1 << logN], h[idx], l[idx]);
}

__global__ void __launch_bounds__(256) packqkv(const float* __restrict__ wq,
                                               const float* __restrict__ wk,
                                               const float* __restrict__ wv,
                                               uint32_t* __restrict__ h,
                                               uint32_t* __restrict__ l)
{
    int idx = blockIdx.x * 256 + threadIdx.x;
    int slab = idx / (256 * NQKV);
    int rem = idx - slab * (256 * NQKV);
    int kp = rem / NQKV;
    int c = rem - kp * NQKV;
    int comp = c >> 12;
    int c2 = c & 4095;
    const float* W = (comp == 0) ? wq : (comp == 1) ? wk : wv;
    W += (size_t)slab * HIDX * HH;
    float a = W[(size_t)(2 * kp) * HH + c2];
    float b = W[(size_t)(2 * kp + 1) * HH + c2];
    split2(a, b, h[idx], l[idx]);
}

__global__ void __launch_bounds__(256) packbias(const float* __restrict__ bq,
                                                const float* __restrict__ bk,
                                                const float* __restrict__ bv,
                                                float* __restrict__ bcat)
{
    int idx = blockIdx.x * 256 + threadIdx.x;
    int slab = idx / NQKV;
    int c = idx - slab * NQKV;
    int comp = c >> 12;
    int c2 = c & 4095;
    const float* src = (comp == 0) ? bq : (comp == 1) ? bk : bv;
    bcat[idx] = src[slab * HH + c2];
}

__device__ __forceinline__ float vread(const uint32_t* __restrict__ vh,
                                       const uint32_t* __restrict__ vl, size_t f)
{
    size_t p = (f >> 12) * 2048 + ((f & 4095) >> 1);
    __nv_bfloat162 h = *(const __nv_bfloat162*)&vh[p];
    __nv_bfloat162 l = *(const __nv_bfloat162*)&vl[p];
    float2 hf = __bfloat1622float2(h);
    float2 lf = __bfloat1622float2(l);
    return (f & 1) ? (hf.y + lf.y) : (hf.x + lf.x);
}

__global__ void __launch_bounds__(256) packv(const uint32_t* __restrict__ vh,
                                             const uint32_t* __restrict__ vl,
                                             uint32_t* __restrict__ h, uint32_t* __restrict__ l)
{
    int idx = blockIdx.x * 256 + threadIdx.x;
    int b  = idx >> 21;
    int hh = (idx >> 18) & 7;
    int jp = (idx >> 9) & 511;
    int d  = idx & 511;
    size_t f = (size_t)b * 4194304 + (size_t)hh * 524288 + (size_t)jp * 1024 + d;
    split2(vread(vh, vl, f), vread(vh, vl, f + 512), h[idx], l[idx]);
}

// gather packed x rows by MoE permutation (padding rows -> 0)
__global__ void __launch_bounds__(256) moe_gather(const uint32_t* __restrict__ xh,
                                                  const uint32_t* __restrict__ xl,
                                                  uint32_t* __restrict__ gh,
                                                  uint32_t* __restrict__ gl)
{
    int idx = blockIdx.x * 256 + threadIdx.x;
    int p = idx >> 8;
    int i = idx & 255;
    int r = g_perm[p];
    gh[idx] = (r >= 0) ? xh[r * 256 + i] : 0u;
    gl[idx] = (r >= 0) ? xl[r * 256 + i] : 0u;
}

// ---------------------------------------------------------------------------
// Softmax over rows of SEQ; writes packed bf16 hi/lo probabilities.
// ---------------------------------------------------------------------------
__global__ void __launch_bounds__(256) softmax_kernel(const float* __restrict__ sc,
                                                      uint32_t* __restrict__ ath,
                                                      uint32_t* __restrict__ atl, int masked)
{
    long long base = (long long)blockIdx.x * SEQ;
    long long pbase = (long long)blockIdx.x * (SEQ / 2);
    int i = blockIdx.x & (SEQ - 1);
    int n = masked ? (i + 1) : SEQ;
    int tid = threadIdx.x;
    __shared__ float red[8];

    float v[2][2];
    float mx = -1e30f;
#pragma unroll
    for (int j = 0; j < 2; j++) {
        int c = (tid + (j << 8)) << 1;
        float2 t = *(const float2*)(sc + base + c);
        v[j][0] = (c < n) ? t.x : -1e30f;
        v[j][1] = (c + 1 < n) ? t.y : -1e30f;
        mx = fmaxf(mx, fmaxf(v[j][0], v[j][1]));
    }
#pragma unroll
    for (int o = 16; o; o >>= 1) mx = fmaxf(mx, __shfl_xor_sync(0xffffffffu, mx, o));
    if ((tid & 31) == 0) red[tid >> 5] = mx;
    __syncthreads();
    mx = red[0];
#pragma unroll
    for (int w = 1; w < 8; w++) mx = fmaxf(mx, red[w]);
    __syncthreads();

    float s = 0.f;
#pragma unroll
    for (int j = 0; j < 2; j++) {
        int c = (tid + (j << 8)) << 1;
        v[j][0] = (c < n) ? __expf(v[j][0] - mx) : 0.f;
        v[j][1] = (c + 1 < n) ? __expf(v[j][1] - mx) : 0.f;
        s += v[j][0] + v[j][1];
    }
#pragma unroll
    for (int o = 16; o; o >>= 1) s += __shfl_xor_sync(0xffffffffu, s, o);
    if ((tid & 31) == 0) red[tid >> 5] = s;
    __syncthreads();
    s = 0.f;
#pragma unroll
    for (int w = 0; w < 8; w++) s += red[w];
    float inv = 1.f / s;
#pragma unroll
    for (int j = 0; j < 2; j++) {
        uint32_t h, l;
        split2(v[j][0] * inv, v[j][1] * inv, h, l);
        ath[pbase + tid + (j << 8)] = h;
        atl[pbase + tid + (j << 8)] = l;
    }
}

// ---------------------------------------------------------------------------
// y = LayerNorm(a + r); also writes packed bf16 hi/lo of y.
// ---------------------------------------------------------------------------
__global__ void __launch_bounds__(256) ln_kernel(
    const float* __restrict__ a, const float* __restrict__ r,
    const float* __restrict__ g, const float* __restrict__ b,
    float* __restrict__ y, uint32_t* __restrict__ yph, uint32_t* __restrict__ ypl)
{
    long long base = (long long)blockIdx.x * HIDX;
    int tid = threadIdx.x;
    int c = tid << 1;
    __shared__ float red[8];

    float2 av = *(const float2*)(a + base + c);
    float2 rv = *(const float2*)(r + base + c);
    float z0 = av.x + rv.x, z1 = av.y + rv.y;
    float s = z0 + z1;
#pragma unroll
    for (int o = 16; o; o >>= 1) s += __shfl_xor_sync(0xffffffffu, s, o);
    if ((tid & 31) == 0) red[tid >> 5] = s;
    __syncthreads();
    s = 0.f;
#pragma unroll
    for (int w = 0; w < 8; w++) s += red[w];
    float m = s * (1.f / HIDX);
    float d0 = z0 - m, d1 = z1 - m;
    float qs = d0 * d0 + d1 * d1;
    __syncthreads();
#pragma unroll
    for (int o = 16; o; o >>= 1) qs += __shfl_xor_sync(0xffffffffu, qs, o);
    if ((tid & 31) == 0) red[tid >> 5] = qs;
    __syncthreads();
    qs = 0.f;
#pragma unroll
    for (int w = 0; w < 8; w++) qs += red[w];
    float inv = rsqrtf(qs * (1.f / HIDX) + EPSV);
    float2 gg = *(const float2*)(g + c);
    float2 bb = *(const float2*)(b + c);
    float o0 = gg.x * d0 * inv + bb.x;
    float o1 = gg.y * d1 * inv + bb.y;
    *(float2*)(y + base + c) = make_float2(o0, o1);
    uint32_t h, l;
    split2(o0, o1, h, l);
    yph[(long long)blockIdx.x * 256 + tid] = h;
    ypl[(long long)blockIdx.x * 256 + tid] = l;
}

// ---------------------------------------------------------------------------
// Gate: softmax over E=8, pick 2nd-largest (faithful TOPK-1 bug).
// ---------------------------------------------------------------------------
__global__ void __launch_bounds__(256) gate_kernel(
    const float* __restrict__ x, const float* __restrict__ gw, const float* __restrict__ gb)
{
    int tok = (blockIdx.x << 3) + (threadIdx.x >> 5);
    int lane = threadIdx.x & 31;
    const float* xr = x + (size_t)tok * HIDX;
    float acc[8] = {0, 0, 0, 0, 0, 0, 0, 0};
    for (int j = lane; j < HIDX; j += 32) {
        float xv = xr[j];
        float4 a0 = *(const float4*)(gw + j * 8);
        float4 a1 = *(const float4*)(gw + j * 8 + 4);
        acc[0] += xv * a0.x; acc[1] += xv * a0.y; acc[2] += xv * a0.z; acc[3] += xv * a0.w;
        acc[4] += xv * a1.x; acc[5] += xv * a1.y; acc[6] += xv * a1.z; acc[7] += xv * a1.w;
    }
#pragma unroll
    for (int e = 0; e < 8; e++)
#pragma unroll
        for (int o = 16; o; o >>= 1) acc[e] += __shfl_xor_sync(0xffffffffu, acc[e], o);
    if (lane == 0) {
        float mx = -1e30f;
#pragma unroll
        for (int e = 0; e < 8; e++) { acc[e] += gb[e]; mx = fmaxf(mx, acc[e]); }
        float p[8];
#pragma unroll
        for (int e = 0; e < 8; e++) p[e] = __expf(acc[e] - mx);
        float v1 = -1.f, v2 = -1.f; int i1 = 0, i2 = 0;
#pragma unroll
        for (int e = 0; e < 8; e++) {
            if (p[e] > v1)      { v2 = v1; i2 = i1; v1 = p[e]; i1 = e; }
            else if (p[e] > v2) { v2 = p[e]; i2 = e; }
        }
        g_sel[tok] = i2;
        g_wsel[tok] = v2 / (v1 + v2);
    }
}

// 128-row-aligned per-expert permutation + tile->expert map (<=40 tiles).
__global__ void __launch_bounds__(256) moe_setup()
{
    __shared__ int cnt[8], cursor[8];
    int tid = threadIdx.x;
    if (tid < 8) cnt[tid] = 0;
    for (int i = tid; i < MAXROWS2; i += 256) g_perm[i] = -1;
    __syncthreads();
    for (int i = tid; i < TOK; i += 256) atomicAdd(&cnt[g_sel[i]], 1);
    __syncthreads();
    if (tid == 0) {
        int base = 0, t = 0;
        for (int e = 0; e < 8; e++) {
            cursor[e] = base;
            int tiles = (cnt[e] + 127) >> 7;
            for (int j = 0; j < tiles; j++) g_texp[t++] = e;
            base += tiles << 7;
        }
        for (; t < MAXT2; t++) g_texp[t] = -1;
    }
    __syncthreads();
    for (int i = tid; i < TOK; i += 256) {
        int e = g_sel[i];
        int p = atomicAdd(&cursor[e], 1);
        g_perm[p] = i;
    }
}

__global__ void __launch_bounds__(256) copy_kernel(float* __restrict__ dst,
                                                   const float* __restrict__ src, int n)
{
    int i = blockIdx.x * 256 + threadIdx.x;
    if (i < n) dst[i] = src[i];
}

// ---------------------------------------------------------------------------
extern "C" void kernel_launch(void* const* d_in, const int* in_sizes, int n_in,
                              void* d_out, int out_size)
{
    const float* x_in = (const float*)d_in[0];
    const float* enc  = (const float*)d_in[1];
    const float* wq = (const float*)d_in[2];
    const float* bq = (const float*)d_in[3];
    const float* wk = (const float*)d_in[4];
    const float* bk = (const float*)d_in[5];
    const float* wv = (const float*)d_in[6];
    const float* bv = (const float*)d_in[7];
    const float* wo = (const float*)d_in[8];
    const float* bo = (const float*)d_in[9];
    const float* gw = (const float*)d_in[10];
    const float* gb = (const float*)d_in[11];
    const float* w1 = (const float*)d_in[12];
    const float* b1 = (const float*)d_in[13];
    const float* w2 = (const float*)d_in[14];
    const float* b2 = (const float*)d_in[15];
    const float* lng = (const float*)d_in[16];
    const float* lnb = (const float*)d_in[17];
    float* out = (float*)d_out;

    cudaFuncSetAttribute(bgemm, cudaFuncAttributeMaxDynamicSharedMemorySize, SMEMSZ);

    float *sc, *t1, *xb, *yb, *bcat;
    uint32_t *qh, *ql, *kh, *kl, *vdh, *vdl, *vph, *vpl, *o2h, *o2l, *ath, *atl;
    uint32_t *xph, *xpl, *eph, *epl, *xgh, *xgl, *hph, *hpl;
    uint32_t *wah, *wal, *woh, *wol, *w1h, *w1l, *w2h, *w2l;
    int *texp, *perm;
    float *wselp;
    cudaGetSymbolAddress((void**)&sc,  g_sc);
    cudaGetSymbolAddress((void**)&t1,  g_t1);
    cudaGetSymbolAddress((void**)&xb,  g_x);
    cudaGetSymbolAddress((void**)&yb,  g_y);
    cudaGetSymbolAddress((void**)&bcat, g_bcat);
    cudaGetSymbolAddress((void**)&qh,  g_qh);  cudaGetSymbolAddress((void**)&ql, g_ql);
    cudaGetSymbolAddress((void**)&kh,  g_kh);  cudaGetSymbolAddress((void**)&kl, g_kl);
    cudaGetSymbolAddress((void**)&vdh, g_vdh); cudaGetSymbolAddress((void**)&vdl, g_vdl);
    cudaGetSymbolAddress((void**)&vph, g_vph); cudaGetSymbolAddress((void**)&vpl, g_vpl);
    cudaGetSymbolAddress((void**)&o2h, g_o2h); cudaGetSymbolAddress((void**)&o2l, g_o2l);
    cudaGetSymbolAddress((void**)&ath, g_ath); cudaGetSymbolAddress((void**)&atl, g_atl);
    cudaGetSymbolAddress((void**)&xph, g_xph); cudaGetSymbolAddress((void**)&xpl, g_xpl);
    cudaGetSymbolAddress((void**)&eph, g_eph); cudaGetSymbolAddress((void**)&epl, g_epl);
    cudaGetSymbolAddress((void**)&xgh, g_xgh); cudaGetSymbolAddress((void**)&xgl, g_xgl);
    cudaGetSymbolAddress((void**)&hph, g_hph); cudaGetSymbolAddress((void**)&hpl, g_hpl);
    cudaGetSymbolAddress((void**)&wah, g_wah); cudaGetSymbolAddress((void**)&wal, g_wal);
    cudaGetSymbolAddress((void**)&woh, g_woh); cudaGetSymbolAddress((void**)&wol, g_wol);
    cudaGetSymbolAddress((void**)&w1h, g_w1h); cudaGetSymbolAddress((void**)&w1l, g_w1l);
    cudaGetSymbolAddress((void**)&w2h, g_w2h); cudaGetSymbolAddress((void**)&w2l, g_w2l);
    cudaGetSymbolAddress((void**)&texp, g_texp);
    cudaGetSymbolAddress((void**)&perm, g_perm);
    cudaGetSymbolAddress((void**)&wselp, g_wsel);

    // one-time packing
    packqkv<<<NL * 2 * 256 * NQKV / 256, 256>>>(wq, wk, wv, wah, wal);
    packbias<<<NL * 2 * NQKV / 256, 256>>>(bq, bk, bv, bcat);
    packcols<<<NL * 2 * (HH / 2) * HIDX / 256, 256>>>(wo, woh, wol, 9);
    packcols<<<NL * NE * 256 * FFN / 256, 256>>>(w1, w1h, w1l, 10);
    packcols<<<NL * NE * 512 * HIDX / 256, 256>>>(w2, w2h, w2l, 9);
    packrows<<<TOK * HIDX / 2 / 256, 256>>>(enc, eph, epl);
    packrows<<<TOK * HIDX / 2 / 256, 256>>>(x_in, xph, xpl);
    copy_kernel<<<TOK * HIDX / 256, 256>>>(xb, x_in, TOK * HIDX);

    for (int l = 0; l < NL; l++) {
        for (int a = 0; a < 2; a++) {
            const uint32_t* aAh = a ? eph : xph;
            const uint32_t* aAl = a ? epl : xpl;
            size_t wP = (size_t)(l * 2 + a) * 256 * NQKV;
            int msk = (a == 0);

            // fused QKV projection (Q,K from aAh; V cols from xph)
            bgemm<<<dim3(NQKV / 64, 32, 1), 256, SMEMSZ>>>(
                aAh, aAl, xph, xpl, 256, 0, 0,
                wah + wP, wal + wP, NQKV, 0, 0,
                nullptr, 0, 0, 0,
                qh, ql, kh, kl, vdh, vdl, 2048, 0, 0,
                bcat + (size_t)(l * 2 + a) * NQKV, HIDX, 0, 0, 0, NOEXTRA);
            packv<<<NB * NH * (SEQ / 2) * HIDX / 256, 256>>>(vdh, vdl, vph, vpl);

            // scores = Q @ K^T per (b,h)
            bgemm<<<dim3(16, 8, 32), 256, SMEMSZ>>>(
                qh, ql, nullptr, nullptr, 256, 2097152, 262144,
                kh, kl, 256, 2097152, 262144,
                sc, SEQ, 8388608, 1048576,
                nullptr, nullptr, nullptr, nullptr, nullptr, nullptr, 0, 0, 0,
                nullptr, HIDX, 1, msk, 0, NOEXTRA);
            softmax_kernel<<<NB * NH * SEQ, 256>>>(sc, ath, atl, msk);

            // O2 = attn @ V -> packed
            bgemm<<<dim3(8, 8, 32), 256, SMEMSZ>>>(
                ath, atl, nullptr, nullptr, 512, 4194304, 524288,
                vph, vpl, 512, 2097152, 262144,
                nullptr, 0, 0, 0,
                o2h, o2l, nullptr, nullptr, nullptr, nullptr, 2048, 2097152, 256,
                nullptr, SEQ, 0, 0, msk, NOEXTRA);

            // out projection
            size_t wPo = (size_t)(l * 2 + a) * 1048576;
            bgemm<<<dim3(8, 32, 1), 256, SMEMSZ>>>(
                o2h, o2l, nullptr, nullptr, 2048, 0, 0,
                woh + wPo, wol + wPo, HIDX, 0, 0,
                t1, HIDX, 0, 0,
                nullptr, nullptr, nullptr, nullptr, nullptr, nullptr, 0, 0, 0,
                bo + (size_t)(l * 2 + a) * HIDX, HH, 0, 0, 0, NOEXTRA);

            ln_kernel<<<TOK, 256>>>(t1, xb, lng + (size_t)(l * 3 + a) * HIDX,
                                    lnb + (size_t)(l * 3 + a) * HIDX, xb, xph, xpl);
        }
        gate_kernel<<<TOK / 8, 256>>>(xb, gw + (size_t)l * HIDX * NE, gb + (size_t)l * NE);
        moe_setup<<<1, 256>>>();
        moe_gather<<<MAXROWS2, 256>>>(xph, xpl, xgh, xgl);

        // MoE gemm1: h = relu(xg @ w1[e] + b1[e]) -> packed, expert per M-tile
        bgemm<<<dim3(FFN / 64, MAXT2, 1), 256, SMEMSZ>>>(
            xgh, xgl, nullptr, nullptr, 256, 0, 0,
            w1h + (size_t)l * 2097152, w1l + (size_t)l * 2097152, FFN, 262144, 0,
            nullptr, 0, 0, 0,
            hph, hpl, nullptr, nullptr, nullptr, nullptr, 512, 0, 0,
            b1 + (size_t)l * NE * FFN, HIDX, 0, 0, 0,
            texp, nullptr, nullptr, 1, FFN);
        // MoE gemm2: y[perm[r]] = (h @ w2[e] + b2[e]) * wsel, scatter
        bgemm<<<dim3(HIDX / 64, MAXT2, 1), 256, SMEMSZ>>>(
            hph, hpl, nullptr, nullptr, 512, 0, 0,
            w2h + (size_t)l * 2097152, w2l + (size_t)l * 2097152, HIDX, 262144, 0,
            yb, HIDX, 0, 0,
            nullptr, nullptr, nullptr, nullptr, nullptr, nullptr, 0, 0, 0,
            b2 + (size_t)l * NE * HIDX, FFN, 0, 0, 0,
            texp, perm, wselp, 0, HIDX);

        float* lnOut = (l == NL - 1) ? out : xb;
        ln_kernel<<<TOK, 256>>>(yb, xb, lng + (size_t)(l * 3 + 2) * HIDX,
                                lnb + (size_t)(l * 3 + 2) * HIDX, lnOut, xph, xpl);
    }
}

// round 17
// speedup vs baseline: 1.0556x; 1.0065x over previous
#include <cuda_runtime.h>
#include <cuda_bf16.h>
#include <cstdint>

#define NL 2
#define NH 8
#define SEQ 1024
#define HIDX 512
#define HH 4096
#define NE 8
#define FFN 1024
#define NB 4
#define TOK 4096
#define EPSV 1e-5f
#define MAXROWS2 5120
#define MAXT2 40
#define SMEMSZ 55296
#define NQKV 12288

// fp32 buffers
static __device__ float g_sc[(size_t)NB * NH * SEQ * SEQ];
static __device__ float g_t1[(size_t)TOK * HIDX];
static __device__ float g_x[(size_t)TOK * HIDX];
static __device__ float g_y[(size_t)TOK * HIDX];
static __device__ float g_bcat[NL * 2 * NQKV];
static __device__ int   g_sel[TOK];
static __device__ float g_wsel[TOK];
static __device__ int   g_perm[MAXROWS2];
static __device__ int   g_texp[MAXT2];

// packed bf16-pair buffers (hi/lo), 16B aligned for cp.async
#define PKA __device__ __align__(16)
static PKA uint32_t g_qh[(size_t)TOK * HH / 2], g_ql[(size_t)TOK * HH / 2];
static PKA uint32_t g_kh[(size_t)TOK * HH / 2], g_kl[(size_t)TOK * HH / 2];
static PKA uint32_t g_vdh[(size_t)TOK * HH / 2], g_vdl[(size_t)TOK * HH / 2];
static PKA uint32_t g_vph[(size_t)NB * NH * (SEQ / 2) * HIDX], g_vpl[(size_t)NB * NH * (SEQ / 2) * HIDX];
static PKA uint32_t g_o2h[(size_t)TOK * HH / 2], g_o2l[(size_t)TOK * HH / 2];
static PKA uint32_t g_ath[(size_t)NB * NH * SEQ * SEQ / 2], g_atl[(size_t)NB * NH * SEQ * SEQ / 2];
static PKA uint32_t g_xph[TOK * HIDX / 2], g_xpl[TOK * HIDX / 2];
static PKA uint32_t g_eph[TOK * HIDX / 2], g_epl[TOK * HIDX / 2];
static PKA uint32_t g_xgh[(size_t)MAXROWS2 * 256], g_xgl[(size_t)MAXROWS2 * 256];
static PKA uint32_t g_hph[(size_t)MAXROWS2 * 512], g_hpl[(size_t)MAXROWS2 * 512];
// fused QKV weights: [slab][256 kp][12288]
static PKA uint32_t g_wah[(size_t)NL * 2 * (HIDX / 2) * NQKV], g_wal[(size_t)NL * 2 * (HIDX / 2) * NQKV];
static PKA uint32_t g_woh[(size_t)NL * 2 * HH / 2 * HIDX], g_wol[(size_t)NL * 2 * HH / 2 * HIDX];
static PKA uint32_t g_w1h[(size_t)NL * NE * 256 * FFN], g_w1l[(size_t)NL * NE * 256 * FFN];
static PKA uint32_t g_w2h[(size_t)NL * NE * 512 * HIDX], g_w2l[(size_t)NL * NE * 512 * HIDX];

__device__ __forceinline__ void split2(float x, float y, uint32_t& hi, uint32_t& lo)
{
    __nv_bfloat162 h = __floats2bfloat162_rn(x, y);
    float2 hf = __bfloat1622float2(h);
    __nv_bfloat162 l = __floats2bfloat162_rn(x - hf.x, y - hf.y);
    hi = *(uint32_t*)&h;
    lo = *(uint32_t*)&l;
}

#define MMA_BF16(d, a, b)                                                     \
    asm volatile(                                                             \
        "mma.sync.aligned.m16n8k16.row.col.f32.bf16.bf16.f32 "                \
        "{%0,%1,%2,%3},{%4,%5,%6,%7},{%8,%9},{%0,%1,%2,%3};"                  \
        : "+f"(d[0]), "+f"(d[1]), "+f"(d[2]), "+f"(d[3])                      \
        : "r"(a[0]), "r"(a[1]), "r"(a[2]), "r"(a[3]), "r"(b[0]), "r"(b[1]))

// ---------------------------------------------------------------------------
// Packed split-bf16 mma.sync GEMM (round-6 proven inner loop, untouched).
// Prologue: A-source select (fused QKV), expert indirection (MoE).
// Epilogue: component select, optional ReLU (packed), optional scatter.
// ---------------------------------------------------------------------------
__global__ void __launch_bounds__(256) bgemm(
    const uint32_t* __restrict__ Ah, const uint32_t* __restrict__ Al,
    const uint32_t* __restrict__ A2h, const uint32_t* __restrict__ A2l,
    int ldaP, long long aSb, long long aSh,
    const uint32_t* __restrict__ Bh, const uint32_t* __restrict__ Bl,
    int ldbB, long long bSb, long long bSh,
    float* __restrict__ C, int ldc, long long cSb, long long cSh,
    uint32_t* __restrict__ Cph, uint32_t* __restrict__ Cpl,
    uint32_t* __restrict__ Cph2, uint32_t* __restrict__ Cpl2,
    uint32_t* __restrict__ Cph3, uint32_t* __restrict__ Cpl3,
    int ldcP, long long cpSb, long long cpSh,
    const float* __restrict__ bias,
    int K, int transB, int causalSkip, int causalK,
    const int* __restrict__ tExp, const int* __restrict__ scatPerm,
    const float* __restrict__ wsel, int doRelu, int biasStride)
{
    int row0 = blockIdx.y * 128;
    int col0 = blockIdx.x * 64;
    if (causalSkip && col0 >= row0 + 128) return;
    if (tExp) {
        int e = tExp[blockIdx.y];
        if (e < 0) return;
        Bh += (long long)e * bSb;
        Bl += (long long)e * bSb;
        if (bias) bias += (long long)e * biasStride;
    }
    long long zb = blockIdx.z >> 3, zh = blockIdx.z & 7;
    if (A2h && col0 >= 8192) { Ah = A2h; Al = A2l; }
    Ah += zb * aSb + zh * aSh;
    Al += zb * aSb + zh * aSh;
    if (!tExp) {
        Bh += zb * bSb + zh * bSh;
        Bl += zb * bSb + zh * bSh;
    }

    extern __shared__ uint32_t sm[];
    uint32_t smBase = (uint32_t)__cvta_generic_to_shared(sm);

    int tid = threadIdx.x;
    int warp = tid >> 5, lane = tid & 31;
    int wm0 = (warp >> 1) << 5;
    int wn0 = (warp & 1) << 5;
    int tg = lane & 3, gp = lane >> 2;

    const uint32_t* pAh = Ah + (long long)(row0 + (tid >> 1)) * ldaP + ((tid & 1) << 2);
    const uint32_t* pAl = Al + (long long)(row0 + (tid >> 1)) * ldaP + ((tid & 1) << 2);
    int aOff = (tid >> 1) * 12 + ((tid & 1) << 2);

    const uint32_t* pB;
    int bOff;
    int bBase = (tid < 128) ? 9216 : 11520;
    int tt = tid & 127;
    long long bStep;
    if (!transB) {
        int kp = tt >> 4, cc = (tt & 15) << 2;
        pB = (tid < 128 ? Bh : Bl) + (long long)kp * ldbB + col0 + cc;
        bOff = kp * 72 + cc;
        bStep = ldbB;
    } else {
        int nn = tt >> 1, cc = (tt & 1) << 2;
        pB = (tid < 128 ? Bh : Bl) + (long long)(col0 + nn) * ldbB + cc;
        bOff = nn * 12 + cc;
        bStep = 1;
    }

#define CPA(doff, src)                                                        \
    asm volatile("cp.async.cg.shared.global [%0], [%1], 16;"                  \
                 :: "r"(smBase + ((doff) << 2)), "l"(src))
#define ISSUE(st, kp0)                                                        \
    do {                                                                      \
        CPA((st) * 1536 + aOff, pAh + (kp0));                                 \
        CPA(4608 + (st) * 1536 + aOff, pAl + (kp0));                          \
        CPA(bBase + (st) * 768 + bOff, pB + (long long)(kp0) * bStep);        \
    } while (0)
#define COMMIT asm volatile("cp.async.commit_group;" ::)

    int kend = causalK ? (row0 + 128) : K;
    int niter = kend >> 4;

    ISSUE(0, 0);
    COMMIT;
    if (niter > 1) ISSUE(1, 8);
    COMMIT;

    float acc[2][4][4];
#pragma unroll
    for (int i = 0; i < 2; i++)
#pragma unroll
        for (int j = 0; j < 4; j++)
#pragma unroll
            for (int t = 0; t < 4; t++) acc[i][j][t] = 0.f;

    for (int i = 0; i < niter; i++) {
        if (i + 1 < niter) asm volatile("cp.async.wait_group 1;" ::);
        else               asm volatile("cp.async.wait_group 0;" ::);
        __syncthreads();
        if (i + 2 < niter) {
            int s2 = (i + 2) % 3;
            ISSUE(s2, (i + 2) * 8);
        }
        COMMIT;

        int s = i % 3;
        const uint32_t* aHs = sm + s * 1536;
        const uint32_t* aLs = sm + 4608 + s * 1536;
        const uint32_t* bHs = sm + 9216 + s * 768;
        const uint32_t* bLs = sm + 11520 + s * 768;

        uint32_t aF[2][4], aG[2][4], bF[4][2], bG[4][2];
#pragma unroll
        for (int mt = 0; mt < 2; mt++) {
            int m = wm0 + mt * 16 + gp;
            aF[mt][0] = aHs[m * 12 + tg];
            aF[mt][1] = aHs[(m + 8) * 12 + tg];
            aF[mt][2] = aHs[m * 12 + tg + 4];
            aF[mt][3] = aHs[(m + 8) * 12 + tg + 4];
            aG[mt][0] = aLs[m * 12 + tg];
            aG[mt][1] = aLs[(m + 8) * 12 + tg];
            aG[mt][2] = aLs[m * 12 + tg + 4];
            aG[mt][3] = aLs[(m + 8) * 12 + tg + 4];
        }
        if (!transB) {
#pragma unroll
            for (int nt = 0; nt < 4; nt++) {
                int n = wn0 + nt * 8 + gp;
                bF[nt][0] = bHs[tg * 72 + n];
                bF[nt][1] = bHs[(tg + 4) * 72 + n];
                bG[nt][0] = bLs[tg * 72 + n];
                bG[nt][1] = bLs[(tg + 4) * 72 + n];
            }
        } else {
#pragma unroll
            for (int nt = 0; nt < 4; nt++) {
                int n = wn0 + nt * 8 + gp;
                bF[nt][0] = bHs[n * 12 + tg];
                bF[nt][1] = bHs[n * 12 + tg + 4];
                bG[nt][0] = bLs[n * 12 + tg];
                bG[nt][1] = bLs[n * 12 + tg + 4];
            }
        }
#pragma unroll
        for (int mt = 0; mt < 2; mt++)
#pragma unroll
            for (int nt = 0; nt < 4; nt++) {
                MMA_BF16(acc[mt][nt], aF[mt], bF[nt]);
                MMA_BF16(acc[mt][nt], aF[mt], bG[nt]);
                MMA_BF16(acc[mt][nt], aG[mt], bF[nt]);
            }
    }

    if (scatPerm) {
#pragma unroll
        for (int mt = 0; mt < 2; mt++) {
            int rl = row0 + wm0 + mt * 16 + gp;
            int rg0 = scatPerm[rl];
            int rg1 = scatPerm[rl + 8];
#pragma unroll
            for (int nt = 0; nt < 4; nt++) {
                int c = col0 + wn0 + nt * 8 + tg * 2;
                float b0 = bias[c], b1v = bias[c + 1];
                if (rg0 >= 0) {
                    float ws = wsel[rg0];
                    *(float2*)(C + (size_t)rg0 * ldc + c) =
                        make_float2((acc[mt][nt][0] + b0) * ws, (acc[mt][nt][1] + b1v) * ws);
                }
                if (rg1 >= 0) {
                    float ws = wsel[rg1];
                    *(float2*)(C + (size_t)rg1 * ldc + c) =
                        make_float2((acc[mt][nt][2] + b0) * ws, (acc[mt][nt][3] + b1v) * ws);
                }
            }
        }
    } else if (Cph) {
        uint32_t* oph = Cph;
        uint32_t* opl = Cpl;
        int cbase = 0;
        if (Cph3 && col0 >= 8192)      { oph = Cph3; opl = Cpl3; cbase = 8192; }
        else if (Cph2 && col0 >= 4096) { oph = Cph2; opl = Cpl2; cbase = 4096; }
        oph += zb * cpSb + zh * cpSh;
        opl += zb * cpSb + zh * cpSh;
#pragma unroll
        for (int mt = 0; mt < 2; mt++) {
            long long r = row0 + wm0 + mt * 16 + gp;
#pragma unroll
            for (int nt = 0; nt < 4; nt++) {
                int c = col0 + wn0 + nt * 8 + tg * 2;
                float b0 = bias ? bias[c] : 0.f;
                float b1 = bias ? bias[c + 1] : 0.f;
                int cp = (c - cbase) >> 1;
                float v0 = acc[mt][nt][0] + b0, v1 = acc[mt][nt][1] + b1;
                float v2 = acc[mt][nt][2] + b0, v3 = acc[mt][nt][3] + b1;
                if (doRelu) {
                    v0 = fmaxf(v0, 0.f); v1 = fmaxf(v1, 0.f);
                    v2 = fmaxf(v2, 0.f); v3 = fmaxf(v3, 0.f);
                }
                uint32_t h, l;
                split2(v0, v1, h, l);
                oph[r * ldcP + cp] = h;
                opl[r * ldcP + cp] = l;
                split2(v2, v3, h, l);
                oph[(r + 8) * ldcP + cp] = h;
                opl[(r + 8) * ldcP + cp] = l;
            }
        }
    } else {
        C += zb * cSb + zh * cSh;
#pragma unroll
        for (int mt = 0; mt < 2; mt++) {
            long long r = row0 + wm0 + mt * 16 + gp;
#pragma unroll
            for (int nt = 0; nt < 4; nt++) {
                int c = col0 + wn0 + nt * 8 + tg * 2;
                float b0 = bias ? bias[c] : 0.f;
                float b1 = bias ? bias[c + 1] : 0.f;
                float2 lo = make_float2(acc[mt][nt][0] + b0, acc[mt][nt][1] + b1);
                float2 hi = make_float2(acc[mt][nt][2] + b0, acc[mt][nt][3] + b1);
                *(float2*)(C + r * ldc + c) = lo;
                *(float2*)(C + (r + 8) * ldc + c) = hi;
            }
        }
    }
#undef CPA
#undef ISSUE
#undef COMMIT
}

#define NOEXTRA nullptr, nullptr, nullptr, 0, 0

// ---------------------------------------------------------------------------
// Pre-split kernels (vectorized: float4 loads, uint4/uint2 stores)
// ---------------------------------------------------------------------------
// rows: each thread converts 2 pairs (4 consecutive floats).
__global__ void __launch_bounds__(256) packrows(const float* __restrict__ src,
                                                uint32_t* __restrict__ h, uint32_t* __restrict__ l)
{
    int idx = blockIdx.x * 256 + threadIdx.x;   // pair-pair index
    float4 v = ((const float4*)src)[idx];
    uint2 hh, ll;
    split2(v.x, v.y, hh.x, ll.x);
    split2(v.z, v.w, hh.y, ll.y);
    ((uint2*)h)[idx] = hh;
    ((uint2*)l)[idx] = ll;
}

// cols: each thread handles 4 consecutive columns of one kp row.
__global__ void __launch_bounds__(256) packcols(const float* __restrict__ src,
                                                uint32_t* __restrict__ h, uint32_t* __restrict__ l,
                                                int logN)
{
    int idx4 = blockIdx.x * 256 + threadIdx.x;  // quad index
    int idx = idx4 << 2;
    int kp = idx >> logN;
    int c = idx & ((1 << logN) - 1);
    const float* p = src + (((size_t)kp * 2) << logN) + c;
    float4 a = *(const float4*)(p);
    float4 b = *(const float4*)(p + (1 << logN));
    uint4 hh, ll;
    split2(a.x, b.x, hh.x, ll.x);
    split2(a.y, b.y, hh.y, ll.y);
    split2(a.z, b.z, hh.z, ll.z);
    split2(a.w, b.w, hh.w, ll.w);
    ((uint4*)h)[idx4] = hh;
    ((uint4*)l)[idx4] = ll;
}

// fused QKV pack: each thread 4 consecutive columns (never crosses comp edge).
__global__ void __launch_bounds__(256) packqkv(const float* __restrict__ wq,
                                               const float* __restrict__ wk,
                                               const float* __restrict__ wv,
                                               uint32_t* __restrict__ h,
                                               uint32_t* __restrict__ l)
{
    int idx4 = blockIdx.x * 256 + threadIdx.x;
    int idx = idx4 << 2;
    int slab = idx / (256 * NQKV);
    int rem = idx - slab * (256 * NQKV);
    int kp = rem / NQKV;
    int c = rem - kp * NQKV;
    int comp = c >> 12;
    int c2 = c & 4095;
    const float* W = (comp == 0) ? wq : (comp == 1) ? wk : wv;
    W += (size_t)slab * HIDX * HH;
    float4 a = *(const float4*)(W + (size_t)(2 * kp) * HH + c2);
    float4 b = *(const float4*)(W + (size_t)(2 * kp + 1) * HH + c2);
    uint4 hh, ll;
    split2(a.x, b.x, hh.x, ll.x);
    split2(a.y, b.y, hh.y, ll.y);
    split2(a.z, b.z, hh.z, ll.z);
    split2(a.w, b.w, hh.w, ll.w);
    ((uint4*)h)[idx4] = hh;
    ((uint4*)l)[idx4] = ll;
}

__global__ void __launch_bounds__(256) packbias(const float* __restrict__ bq,
                                                const float* __restrict__ bk,
                                                const float* __restrict__ bv,
                                                float* __restrict__ bcat)
{
    int idx = blockIdx.x * 256 + threadIdx.x;
    int slab = idx / NQKV;
    int c = idx - slab * NQKV;
    int comp = c >> 12;
    int c2 = c & 4095;
    const float* src = (comp == 0) ? bq : (comp == 1) ? bk : bv;
    bcat[idx] = src[slab * HH + c2];
}

__device__ __forceinline__ float vread(const uint32_t* __restrict__ vh,
                                       const uint32_t* __restrict__ vl, size_t f)
{
    size_t p = (f >> 12) * 2048 + ((f & 4095) >> 1);
    __nv_bfloat162 h = *(const __nv_bfloat162*)&vh[p];
    __nv_bfloat162 l = *(const __nv_bfloat162*)&vl[p];
    float2 hf = __bfloat1622float2(h);
    float2 lf = __bfloat1622float2(l);
    return (f & 1) ? (hf.y + lf.y) : (hf.x + lf.x);
}

__global__ void __launch_bounds__(256) packv(const uint32_t* __restrict__ vh,
                                             const uint32_t* __restrict__ vl,
                                             uint32_t* __restrict__ h, uint32_t* __restrict__ l)
{
    int idx = blockIdx.x * 256 + threadIdx.x;
    int b  = idx >> 21;
    int hh = (idx >> 18) & 7;
    int jp = (idx >> 9) & 511;
    int d  = idx & 511;
    size_t f = (size_t)b * 4194304 + (size_t)hh * 524288 + (size_t)jp * 1024 + d;
    split2(vread(vh, vl, f), vread(vh, vl, f + 512), h[idx], l[idx]);
}

// gather packed x rows by MoE permutation (padding rows -> 0)
__global__ void __launch_bounds__(256) moe_gather(const uint32_t* __restrict__ xh,
                                                  const uint32_t* __restrict__ xl,
                                                  uint32_t* __restrict__ gh,
                                                  uint32_t* __restrict__ gl)
{
    int idx = blockIdx.x * 256 + threadIdx.x;
    int p = idx >> 8;
    int i = idx & 255;
    int r = g_perm[p];
    gh[idx] = (r >= 0) ? xh[r * 256 + i] : 0u;
    gl[idx] = (r >= 0) ? xl[r * 256 + i] : 0u;
}

// ---------------------------------------------------------------------------
// Softmax over rows of SEQ; loads guarded for masked region; writes packed.
// ---------------------------------------------------------------------------
__global__ void __launch_bounds__(256) softmax_kernel(const float* __restrict__ sc,
                                                      uint32_t* __restrict__ ath,
                                                      uint32_t* __restrict__ atl, int masked)
{
    long long base = (long long)blockIdx.x * SEQ;
    long long pbase = (long long)blockIdx.x * (SEQ / 2);
    int i = blockIdx.x & (SEQ - 1);
    int n = masked ? (i + 1) : SEQ;
    int tid = threadIdx.x;
    __shared__ float red[8];

    float v[2][2];
    float mx = -1e30f;
#pragma unroll
    for (int j = 0; j < 2; j++) {
        int c = (tid + (j << 8)) << 1;
        if (c < n) {
            float2 t = *(const float2*)(sc + base + c);
            v[j][0] = t.x;
            v[j][1] = (c + 1 < n) ? t.y : -1e30f;
        } else {
            v[j][0] = -1e30f;
            v[j][1] = -1e30f;
        }
        mx = fmaxf(mx, fmaxf(v[j][0], v[j][1]));
    }
#pragma unroll
    for (int o = 16; o; o >>= 1) mx = fmaxf(mx, __shfl_xor_sync(0xffffffffu, mx, o));
    if ((tid & 31) == 0) red[tid >> 5] = mx;
    __syncthreads();
    mx = red[0];
#pragma unroll
    for (int w = 1; w < 8; w++) mx = fmaxf(mx, red[w]);
    __syncthreads();

    float s = 0.f;
#pragma unroll
    for (int j = 0; j < 2; j++) {
        int c = (tid + (j << 8)) << 1;
        v[j][0] = (c < n) ? __expf(v[j][0] - mx) : 0.f;
        v[j][1] = (c + 1 < n) ? __expf(v[j][1] - mx) : 0.f;
        s += v[j][0] + v[j][1];
    }
#pragma unroll
    for (int o = 16; o; o >>= 1) s += __shfl_xor_sync(0xffffffffu, s, o);
    if ((tid & 31) == 0) red[tid >> 5] = s;
    __syncthreads();
    s = 0.f;
#pragma unroll
    for (int w = 0; w < 8; w++) s += red[w];
    float inv = 1.f / s;
#pragma unroll
    for (int j = 0; j < 2; j++) {
        uint32_t h, l;
        split2(v[j][0] * inv, v[j][1] * inv, h, l);
        ath[pbase + tid + (j << 8)] = h;
        atl[pbase + tid + (j << 8)] = l;
    }
}

// ---------------------------------------------------------------------------
// y = LayerNorm(a + r); optionally writes packed bf16 hi/lo of y.
// ---------------------------------------------------------------------------
__global__ void __launch_bounds__(256) ln_kernel(
    const float* __restrict__ a, const float* __restrict__ r,
    const float* __restrict__ g, const float* __restrict__ b,
    float* __restrict__ y, uint32_t* __restrict__ yph, uint32_t* __restrict__ ypl)
{
    long long base = (long long)blockIdx.x * HIDX;
    int tid = threadIdx.x;
    int c = tid << 1;
    __shared__ float red[8];

    float2 av = *(const float2*)(a + base + c);
    float2 rv = *(const float2*)(r + base + c);
    float z0 = av.x + rv.x, z1 = av.y + rv.y;
    float s = z0 + z1;
#pragma unroll
    for (int o = 16; o; o >>= 1) s += __shfl_xor_sync(0xffffffffu, s, o);
    if ((tid & 31) == 0) red[tid >> 5] = s;
    __syncthreads();
    s = 0.f;
#pragma unroll
    for (int w = 0; w < 8; w++) s += red[w];
    float m = s * (1.f / HIDX);
    float d0 = z0 - m, d1 = z1 - m;
    float qs = d0 * d0 + d1 * d1;
    __syncthreads();
#pragma unroll
    for (int o = 16; o; o >>= 1) qs += __shfl_xor_sync(0xffffffffu, qs, o);
    if ((tid & 31) == 0) red[tid >> 5] = qs;
    __syncthreads();
    qs = 0.f;
#pragma unroll
    for (int w = 0; w < 8; w++) qs += red[w];
    float inv = rsqrtf(qs * (1.f / HIDX) + EPSV);
    float2 gg = *(const float2*)(g + c);
    float2 bb = *(const float2*)(b + c);
    float o0 = gg.x * d0 * inv + bb.x;
    float o1 = gg.y * d1 * inv + bb.y;
    *(float2*)(y + base + c) = make_float2(o0, o1);
    if (yph) {
        uint32_t h, l;
        split2(o0, o1, h, l);
        yph[(long long)blockIdx.x * 256 + tid] = h;
        ypl[(long long)blockIdx.x * 256 + tid] = l;
    }
}

// ---------------------------------------------------------------------------
// Gate: softmax over E=8, pick 2nd-largest (faithful TOPK-1 bug).
// ---------------------------------------------------------------------------
__global__ void __launch_bounds__(256) gate_kernel(
    const float* __restrict__ x, const float* __restrict__ gw, const float* __restrict__ gb)
{
    int tok = (blockIdx.x << 3) + (threadIdx.x >> 5);
    int lane = threadIdx.x & 31;
    const float* xr = x + (size_t)tok * HIDX;
    float acc[8] = {0, 0, 0, 0, 0, 0, 0, 0};
    for (int j = lane; j < HIDX; j += 32) {
        float xv = xr[j];
        float4 a0 = *(const float4*)(gw + j * 8);
        float4 a1 = *(const float4*)(gw + j * 8 + 4);
        acc[0] += xv * a0.x; acc[1] += xv * a0.y; acc[2] += xv * a0.z; acc[3] += xv * a0.w;
        acc[4] += xv * a1.x; acc[5] += xv * a1.y; acc[6] += xv * a1.z; acc[7] += xv * a1.w;
    }
#pragma unroll
    for (int e = 0; e < 8; e++)
#pragma unroll
        for (int o = 16; o; o >>= 1) acc[e] += __shfl_xor_sync(0xffffffffu, acc[e], o);
    if (lane == 0) {
        float mx = -1e30f;
#pragma unroll
        for (int e = 0; e < 8; e++) { acc[e] += gb[e]; mx = fmaxf(mx, acc[e]); }
        float p[8];
#pragma unroll
        for (int e = 0; e < 8; e++) p[e] = __expf(acc[e] - mx);
        float v1 = -1.f, v2 = -1.f; int i1 = 0, i2 = 0;
#pragma unroll
        for (int e = 0; e < 8; e++) {
            if (p[e] > v1)      { v2 = v1; i2 = i1; v1 = p[e]; i1 = e; }
            else if (p[e] > v2) { v2 = p[e]; i2 = e; }
        }
        g_sel[tok] = i2;
        g_wsel[tok] = v2 / (v1 + v2);
    }
}

// 128-row-aligned per-expert permutation + tile->expert map (<=40 tiles).
__global__ void __launch_bounds__(256) moe_setup()
{
    __shared__ int cnt[8], cursor[8];
    int tid = threadIdx.x;
    if (tid < 8) cnt[tid] = 0;
    for (int i = tid; i < MAXROWS2; i += 256) g_perm[i] = -1;
    __syncthreads();
    for (int i = tid; i < TOK; i += 256) atomicAdd(&cnt[g_sel[i]], 1);
    __syncthreads();
    if (tid == 0) {
        int base = 0, t = 0;
        for (int e = 0; e < 8; e++) {
            cursor[e] = base;
            int tiles = (cnt[e] + 127) >> 7;
            for (int j = 0; j < tiles; j++) g_texp[t++] = e;
            base += tiles << 7;
        }
        for (; t < MAXT2; t++) g_texp[t] = -1;
    }
    __syncthreads();
    for (int i = tid; i < TOK; i += 256) {
        int e = g_sel[i];
        int p = atomicAdd(&cursor[e], 1);
        g_perm[p] = i;
    }
}

__global__ void __launch_bounds__(256) copy_kernel(float* __restrict__ dst,
                                                   const float* __restrict__ src, int n)
{
    int i = blockIdx.x * 256 + threadIdx.x;
    if (i < n) dst[i] = src[i];
}

// ---------------------------------------------------------------------------
extern "C" void kernel_launch(void* const* d_in, const int* in_sizes, int n_in,
                              void* d_out, int out_size)
{
    const float* x_in = (const float*)d_in[0];
    const float* enc  = (const float*)d_in[1];
    const float* wq = (const float*)d_in[2];
    const float* bq = (const float*)d_in[3];
    const float* wk = (const float*)d_in[4];
    const float* bk = (const float*)d_in[5];
    const float* wv = (const float*)d_in[6];
    const float* bv = (const float*)d_in[7];
    const float* wo = (const float*)d_in[8];
    const float* bo = (const float*)d_in[9];
    const float* gw = (const float*)d_in[10];
    const float* gb = (const float*)d_in[11];
    const float* w1 = (const float*)d_in[12];
    const float* b1 = (const float*)d_in[13];
    const float* w2 = (const float*)d_in[14];
    const float* b2 = (const float*)d_in[15];
    const float* lng = (const float*)d_in[16];
    const float* lnb = (const float*)d_in[17];
    float* out = (float*)d_out;

    cudaFuncSetAttribute(bgemm, cudaFuncAttributeMaxDynamicSharedMemorySize, SMEMSZ);

    float *sc, *t1, *xb, *yb, *bcat;
    uint32_t *qh, *ql, *kh, *kl, *vdh, *vdl, *vph, *vpl, *o2h, *o2l, *ath, *atl;
    uint32_t *xph, *xpl, *eph, *epl, *xgh, *xgl, *hph, *hpl;
    uint32_t *wah, *wal, *woh, *wol, *w1h, *w1l, *w2h, *w2l;
    int *texp, *perm;
    float *wselp;
    cudaGetSymbolAddress((void**)&sc,  g_sc);
    cudaGetSymbolAddress((void**)&t1,  g_t1);
    cudaGetSymbolAddress((void**)&xb,  g_x);
    cudaGetSymbolAddress((void**)&yb,  g_y);
    cudaGetSymbolAddress((void**)&bcat, g_bcat);
    cudaGetSymbolAddress((void**)&qh,  g_qh);  cudaGetSymbolAddress((void**)&ql, g_ql);
    cudaGetSymbolAddress((void**)&kh,  g_kh);  cudaGetSymbolAddress((void**)&kl, g_kl);
    cudaGetSymbolAddress((void**)&vdh, g_vdh); cudaGetSymbolAddress((void**)&vdl, g_vdl);
    cudaGetSymbolAddress((void**)&vph, g_vph); cudaGetSymbolAddress((void**)&vpl, g_vpl);
    cudaGetSymbolAddress((void**)&o2h, g_o2h); cudaGetSymbolAddress((void**)&o2l, g_o2l);
    cudaGetSymbolAddress((void**)&ath, g_ath); cudaGetSymbolAddress((void**)&atl, g_atl);
    cudaGetSymbolAddress((void**)&xph, g_xph); cudaGetSymbolAddress((void**)&xpl, g_xpl);
    cudaGetSymbolAddress((void**)&eph, g_eph); cudaGetSymbolAddress((void**)&epl, g_epl);
    cudaGetSymbolAddress((void**)&xgh, g_xgh); cudaGetSymbolAddress((void**)&xgl, g_xgl);
    cudaGetSymbolAddress((void**)&hph, g_hph); cudaGetSymbolAddress((void**)&hpl, g_hpl);
    cudaGetSymbolAddress((void**)&wah, g_wah); cudaGetSymbolAddress((void**)&wal, g_wal);
    cudaGetSymbolAddress((void**)&woh, g_woh); cudaGetSymbolAddress((void**)&wol, g_wol);
    cudaGetSymbolAddress((void**)&w1h, g_w1h); cudaGetSymbolAddress((void**)&w1l, g_w1l);
    cudaGetSymbolAddress((void**)&w2h, g_w2h); cudaGetSymbolAddress((void**)&w2l, g_w2l);
    cudaGetSymbolAddress((void**)&texp, g_texp);
    cudaGetSymbolAddress((void**)&perm, g_perm);
    cudaGetSymbolAddress((void**)&wselp, g_wsel);

    // one-time packing (vectorized: grid /4 for cols/qkv, /2 for rows)
    packqkv<<<NL * 2 * 256 * NQKV / 1024, 256>>>(wq, wk, wv, wah, wal);
    packbias<<<NL * 2 * NQKV / 256, 256>>>(bq, bk, bv, bcat);
    packcols<<<NL * 2 * (HH / 2) * HIDX / 1024, 256>>>(wo, woh, wol, 9);
    packcols<<<NL * NE * 256 * FFN / 1024, 256>>>(w1, w1h, w1l, 10);
    packcols<<<NL * NE * 512 * HIDX / 1024, 256>>>(w2, w2h, w2l, 9);
    packrows<<<TOK * HIDX / 4 / 256, 256>>>(enc, eph, epl);
    packrows<<<TOK * HIDX / 4 / 256, 256>>>(x_in, xph, xpl);
    copy_kernel<<<TOK * HIDX / 256, 256>>>(xb, x_in, TOK * HIDX);

    for (int l = 0; l < NL; l++) {
        for (int a = 0; a < 2; a++) {
            const uint32_t* aAh = a ? eph : xph;
            const uint32_t* aAl = a ? epl : xpl;
            size_t wP = (size_t)(l * 2 + a) * 256 * NQKV;
            int msk = (a == 0);

            // fused QKV projection (Q,K from aAh; V cols from xph)
            bgemm<<<dim3(NQKV / 64, 32, 1), 256, SMEMSZ>>>(
                aAh, aAl, xph, xpl, 256, 0, 0,
                wah + wP, wal + wP, NQKV, 0, 0,
                nullptr, 0, 0, 0,
                qh, ql, kh, kl, vdh, vdl, 2048, 0, 0,
                bcat + (size_t)(l * 2 + a) * NQKV, HIDX, 0, 0, 0, NOEXTRA);
            packv<<<NB * NH * (SEQ / 2) * HIDX / 256, 256>>>(vdh, vdl, vph, vpl);

            // scores = Q @ K^T per (b,h)
            bgemm<<<dim3(16, 8, 32), 256, SMEMSZ>>>(
                qh, ql, nullptr, nullptr, 256, 2097152, 262144,
                kh, kl, 256, 2097152, 262144,
                sc, SEQ, 8388608, 1048576,
                nullptr, nullptr, nullptr, nullptr, nullptr, nullptr, 0, 0, 0,
                nullptr, HIDX, 1, msk, 0, NOEXTRA);
            softmax_kernel<<<NB * NH * SEQ, 256>>>(sc, ath, atl, msk);

            // O2 = attn @ V -> packed
            bgemm<<<dim3(8, 8, 32), 256, SMEMSZ>>>(
                ath, atl, nullptr, nullptr, 512, 4194304, 524288,
                vph, vpl, 512, 2097152, 262144,
                nullptr, 0, 0, 0,
                o2h, o2l, nullptr, nullptr, nullptr, nullptr, 2048, 2097152, 256,
                nullptr, SEQ, 0, 0, msk, NOEXTRA);

            // out projection
            size_t wPo = (size_t)(l * 2 + a) * 1048576;
            bgemm<<<dim3(8, 32, 1), 256, SMEMSZ>>>(
                o2h, o2l, nullptr, nullptr, 2048, 0, 0,
                woh + wPo, wol + wPo, HIDX, 0, 0,
                t1, HIDX, 0, 0,
                nullptr, nullptr, nullptr, nullptr, nullptr, nullptr, 0, 0, 0,
                bo + (size_t)(l * 2 + a) * HIDX, HH, 0, 0, 0, NOEXTRA);

            ln_kernel<<<TOK, 256>>>(t1, xb, lng + (size_t)(l * 3 + a) * HIDX,
                                    lnb + (size_t)(l * 3 + a) * HIDX, xb, xph, xpl);
        }
        gate_kernel<<<TOK / 8, 256>>>(xb, gw + (size_t)l * HIDX * NE, gb + (size_t)l * NE);
        moe_setup<<<1, 256>>>();
        moe_gather<<<MAXROWS2, 256>>>(xph, xpl, xgh, xgl);

        // MoE gemm1: h = relu(xg @ w1[e] + b1[e]) -> packed, expert per M-tile
        bgemm<<<dim3(FFN / 64, MAXT2, 1), 256, SMEMSZ>>>(
            xgh, xgl, nullptr, nullptr, 256, 0, 0,
            w1h + (size_t)l * 2097152, w1l + (size_t)l * 2097152, FFN, 262144, 0,
            nullptr, 0, 0, 0,
            hph, hpl, nullptr, nullptr, nullptr, nullptr, 512, 0, 0,
            b1 + (size_t)l * NE * FFN, HIDX, 0, 0, 0,
            texp, nullptr, nullptr, 1, FFN);
        // MoE gemm2: y[perm[r]] = (h @ w2[e] + b2[e]) * wsel, scatter
        bgemm<<<dim3(HIDX / 64, MAXT2, 1), 256, SMEMSZ>>>(
            hph, hpl, nullptr, nullptr, 512, 0, 0,
            w2h + (size_t)l * 2097152, w2l + (size_t)l * 2097152, HIDX, 262144, 0,
            yb, HIDX, 0, 0,
            nullptr, nullptr, nullptr, nullptr, nullptr, nullptr, 0, 0, 0,
            b2 + (size_t)l * NE * HIDX, FFN, 0, 0, 0,
            texp, perm, wselp, 0, HIDX);

        int last = (l == NL - 1);
        float* lnOut = last ? out : xb;
        ln_kernel<<<TOK, 256>>>(yb, xb, lng + (size_t)(l * 3 + 2) * HIDX,
                                lnb + (size_t)(l * 3 + 2) * HIDX, lnOut,
                                last ? nullptr : xph, last ? nullptr : xpl);
    }
}